// round 1
// baseline (speedup 1.0000x reference)
#include <cuda_runtime.h>
#include <math.h>

#define MTOK 262144   // B*H*W = 4*256*256
#define CDIM 128
#define HID  512

// ---------------- scratch (device globals: allocation-free) ----------------
__device__ float g_xw[(size_t)MTOK*CDIM];  // LN1 + shifted window-partitioned tokens
__device__ float g_q [(size_t)MTOK*CDIM];
__device__ float g_k [(size_t)MTOK*CDIM];
__device__ float g_v [(size_t)MTOK*CDIM];
__device__ float g_ao[(size_t)MTOK*CDIM];  // attention output (window order)
__device__ float g_xr[(size_t)MTOK*CDIM];  // shortcut + proj (original order)
__device__ float g_l2[(size_t)MTOK*CDIM];  // LN2 output
__device__ float g_h [(size_t)MTOK*HID];   // gelu(fc1)

__device__ __forceinline__ int region(int a) { return a < 248 ? 0 : (a < 252 ? 1 : 2); }

// ---------------- LayerNorm (optionally fused with shift+window gather) ----
// 8 tokens per 256-thread block, one warp per token, float4 per lane.
__global__ void ln_kernel(const float* __restrict__ in, const float* __restrict__ gamma,
                          const float* __restrict__ beta, float* __restrict__ out, int gather)
{
    int token = blockIdx.x * 8 + (threadIdx.x >> 5);
    int lane  = threadIdx.x & 31;
    int src = token;
    if (gather) {
        // token is window-order index (b, wh, ww, ti, tj); source is original
        // grid position after roll(-4,-4):  src = (b, (wh*8+ti+4)%256, (ww*8+tj+4)%256)
        int b = token >> 16, w = (token >> 6) & 1023, t = token & 63;
        int wh = w >> 5, ww = w & 31, ti = t >> 3, tj = t & 7;
        int r = (wh*8 + ti + 4) & 255;
        int c = (ww*8 + tj + 4) & 255;
        src = (b << 16) | (r << 8) | c;
    }
    float4 xv = ((const float4*)in)[(size_t)src*32 + lane];
    float s  = xv.x + xv.y + xv.z + xv.w;
    float sq = xv.x*xv.x + xv.y*xv.y + xv.z*xv.z + xv.w*xv.w;
    #pragma unroll
    for (int o = 16; o; o >>= 1) {
        s  += __shfl_xor_sync(0xffffffffu, s,  o);
        sq += __shfl_xor_sync(0xffffffffu, sq, o);
    }
    float mean = s * (1.f/128.f);
    float var  = sq * (1.f/128.f) - mean*mean;
    float rstd = rsqrtf(var + 1e-5f);
    float4 g  = ((const float4*)gamma)[lane];
    float4 bt = ((const float4*)beta)[lane];
    float4 ov;
    ov.x = (xv.x - mean)*rstd*g.x + bt.x;
    ov.y = (xv.y - mean)*rstd*g.y + bt.y;
    ov.z = (xv.z - mean)*rstd*g.z + bt.z;
    ov.w = (xv.w - mean)*rstd*g.w + bt.w;
    ((float4*)out)[(size_t)token*32 + lane] = ov;
}

// ---------------- generic tiled fp32 GEMM: C[M,N] = A[M,K] @ B[K,N] --------
// modes: 0: (acc+bias)*scale            (QKV; scale folds 1/sqrt(hd) for Q)
//        1: add[perm(m)] + acc + bias   (proj + window-reverse/unshift + shortcut)
//        2: gelu(acc+bias)              (fc1)
//        3: add[m] + acc + bias         (fc2 + residual)
__global__ void gemm_kernel(const float* __restrict__ A, const float* __restrict__ Bw,
                            const float* __restrict__ bias, float* __restrict__ Cout,
                            int N, int K, float scale, int mode,
                            const float* __restrict__ add)
{
    __shared__ float As[64][68];   // pad 4 -> 272B row stride: float4-aligned, no bank conflict
    __shared__ float Bs[64][64];
    const int tx = threadIdx.x, ty = threadIdx.y;
    const int tid = ty*16 + tx;
    const int m0 = blockIdx.y * 64;
    const int n0 = blockIdx.x * 64;
    float acc[4][4] = {};

    for (int kt = 0; kt < K; kt += 64) {
        #pragma unroll
        for (int i = 0; i < 4; i++) {
            int idx = tid + i*256;          // 0..1023 float4 slots of 64x64 tile
            int row = idx >> 4;
            int c4  = (idx & 15) << 2;
            *(float4*)&As[row][c4] = *(const float4*)(A  + (size_t)(m0+row)*K + kt + c4);
            *(float4*)&Bs[row][c4] = *(const float4*)(Bw + (size_t)(kt+row)*N + n0 + c4);
        }
        __syncthreads();
        #pragma unroll
        for (int kk = 0; kk < 64; kk++) {
            float4 b4 = *(const float4*)&Bs[kk][tx << 2];
            float a0 = As[(ty<<2)+0][kk];
            float a1 = As[(ty<<2)+1][kk];
            float a2 = As[(ty<<2)+2][kk];
            float a3 = As[(ty<<2)+3][kk];
            acc[0][0] += a0*b4.x; acc[0][1] += a0*b4.y; acc[0][2] += a0*b4.z; acc[0][3] += a0*b4.w;
            acc[1][0] += a1*b4.x; acc[1][1] += a1*b4.y; acc[1][2] += a1*b4.z; acc[1][3] += a1*b4.w;
            acc[2][0] += a2*b4.x; acc[2][1] += a2*b4.y; acc[2][2] += a2*b4.z; acc[2][3] += a2*b4.w;
            acc[3][0] += a3*b4.x; acc[3][1] += a3*b4.y; acc[3][2] += a3*b4.z; acc[3][3] += a3*b4.w;
        }
        __syncthreads();
    }

    #pragma unroll
    for (int r = 0; r < 4; r++) {
        int m = m0 + (ty<<2) + r;
        size_t dstrow;
        if (mode == 1) {
            // window order -> original token order (window reverse + roll(+4,+4))
            int b = m >> 16, w = (m >> 6) & 1023, t = m & 63;
            int wh = w >> 5, ww = w & 31, ti = t >> 3, tj = t & 7;
            int rr = (wh*8 + ti + 4) & 255;
            int cc = (ww*8 + tj + 4) & 255;
            dstrow = (size_t)((b << 16) | (rr << 8) | cc) * N;
        } else {
            dstrow = (size_t)m * N;
        }
        #pragma unroll
        for (int c = 0; c < 4; c++) {
            int n = n0 + (tx<<2) + c;
            float val = acc[r][c] + bias[n];
            if (mode == 0)      val *= scale;
            else if (mode == 2) val = 0.5f*val*(1.0f + erff(val*0.70710678118654752f));
            else                val += add[dstrow + n];   // modes 1,3
            Cout[dstrow + n] = val;
        }
    }
}

// ---------------- windowed attention: one block per (window, head) ---------
// 64 threads; thread = one query token. Bias index and shift-mask labels are
// computed analytically (REL_IDX: (dqi+7)*15 + (dqj+7); labels from region()).
__global__ void attn_kernel(const float* __restrict__ q, const float* __restrict__ k,
                            const float* __restrict__ v, const float* __restrict__ rpb,
                            float* __restrict__ out)
{
    __shared__ float ks[64][32];
    __shared__ float vs[64][32];
    __shared__ float sc[64][65];
    __shared__ int   lab[64];
    int win  = blockIdx.x >> 2;
    int head = blockIdx.x & 3;
    int t = threadIdx.x;                  // query index 0..63
    int wloc = win & 1023;
    int wh = wloc >> 5, ww = wloc & 31;
    int ti = t >> 3, tj = t & 7;
    size_t rowbase = ((size_t)win*64 + t)*128 + head*32;

    float qr[32];
    #pragma unroll
    for (int d4 = 0; d4 < 8; d4++) {
        float4 qv = *(const float4*)(q + rowbase + d4*4);
        qr[d4*4+0]=qv.x; qr[d4*4+1]=qv.y; qr[d4*4+2]=qv.z; qr[d4*4+3]=qv.w;
        *(float4*)&ks[t][d4*4] = *(const float4*)(k + rowbase + d4*4);
        *(float4*)&vs[t][d4*4] = *(const float4*)(v + rowbase + d4*4);
    }
    lab[t] = 3*region(wh*8 + ti) + region(ww*8 + tj);
    __syncthreads();

    int myl = lab[t];
    float mx = -1e30f;
    for (int j = 0; j < 64; j++) {
        float dot = 0.f;
        #pragma unroll
        for (int d4 = 0; d4 < 8; d4++) {
            float4 kv = *(const float4*)&ks[j][d4*4];
            dot += qr[d4*4+0]*kv.x + qr[d4*4+1]*kv.y + qr[d4*4+2]*kv.z + qr[d4*4+3]*kv.w;
        }
        int ki = j >> 3, kj = j & 7;
        int bidx = (ti - ki + 7)*15 + (tj - kj + 7);
        float s = dot + rpb[bidx*4 + head];
        if (lab[j] != myl) s -= 100.f;
        sc[t][j] = s;
        mx = fmaxf(mx, s);
    }
    float sum = 0.f;
    for (int j = 0; j < 64; j++) {
        float e = __expf(sc[t][j] - mx);
        sc[t][j] = e;
        sum += e;
    }
    float inv = 1.f/sum;

    float o[32];
    #pragma unroll
    for (int d = 0; d < 32; d++) o[d] = 0.f;
    for (int j = 0; j < 64; j++) {
        float p = sc[t][j];
        #pragma unroll
        for (int d4 = 0; d4 < 8; d4++) {
            float4 vv = *(const float4*)&vs[j][d4*4];
            o[d4*4+0] += p*vv.x; o[d4*4+1] += p*vv.y; o[d4*4+2] += p*vv.z; o[d4*4+3] += p*vv.w;
        }
    }
    #pragma unroll
    for (int d4 = 0; d4 < 8; d4++) {
        float4 ov = make_float4(o[d4*4]*inv, o[d4*4+1]*inv, o[d4*4+2]*inv, o[d4*4+3]*inv);
        *(float4*)(out + rowbase + d4*4) = ov;
    }
}

// ---------------------------------------------------------------------------
extern "C" void kernel_launch(void* const* d_in, const int* in_sizes, int n_in,
                              void* d_out, int out_size)
{
    const float* hs   = (const float*)d_in[0];
    const float* l1s  = (const float*)d_in[1];
    const float* l1b  = (const float*)d_in[2];
    const float* qw   = (const float*)d_in[3];
    const float* qb   = (const float*)d_in[4];
    const float* kw   = (const float*)d_in[5];
    const float* kb   = (const float*)d_in[6];
    const float* vw   = (const float*)d_in[7];
    const float* vb   = (const float*)d_in[8];
    const float* pw   = (const float*)d_in[9];
    const float* pb   = (const float*)d_in[10];
    const float* rpb  = (const float*)d_in[11];
    const float* l2s  = (const float*)d_in[12];
    const float* l2b  = (const float*)d_in[13];
    const float* f1w  = (const float*)d_in[14];
    const float* f1b  = (const float*)d_in[15];
    const float* f2w  = (const float*)d_in[16];
    const float* f2b  = (const float*)d_in[17];
    float* outp = (float*)d_out;

    float *xw, *qx, *kx, *vx, *ao, *xr, *l2, *hbuf;
    cudaGetSymbolAddress((void**)&xw,   g_xw);
    cudaGetSymbolAddress((void**)&qx,   g_q);
    cudaGetSymbolAddress((void**)&kx,   g_k);
    cudaGetSymbolAddress((void**)&vx,   g_v);
    cudaGetSymbolAddress((void**)&ao,   g_ao);
    cudaGetSymbolAddress((void**)&xr,   g_xr);
    cudaGetSymbolAddress((void**)&l2,   g_l2);
    cudaGetSymbolAddress((void**)&hbuf, g_h);

    const float qscale = 0.17677669529663687f;  // 1/sqrt(32)
    dim3 gblk(16, 16);
    dim3 g128(128/64, MTOK/64);   // (2, 4096)
    dim3 g512(512/64, MTOK/64);   // (8, 4096)

    // 1. LN1 + shift + window partition
    ln_kernel<<<MTOK/8, 256>>>(hs, l1s, l1b, xw, 1);
    // 2-4. Q, K, V projections (Q scaled)
    gemm_kernel<<<g128, gblk>>>(xw, qw, qb, qx, 128, 128, qscale, 0, nullptr);
    gemm_kernel<<<g128, gblk>>>(xw, kw, kb, kx, 128, 128, 1.0f,   0, nullptr);
    gemm_kernel<<<g128, gblk>>>(xw, vw, vb, vx, 128, 128, 1.0f,   0, nullptr);
    // 5. windowed attention with rel-pos bias + shift mask
    attn_kernel<<<4096*4, 64>>>(qx, kx, vx, rpb, ao);
    // 6. proj + window-reverse/unshift + shortcut add -> x (original order)
    gemm_kernel<<<g128, gblk>>>(ao, pw, pb, xr, 128, 128, 1.0f, 1, hs);
    // 7. LN2
    ln_kernel<<<MTOK/8, 256>>>(xr, l2s, l2b, l2, 0);
    // 8. fc1 + GELU
    gemm_kernel<<<g512, gblk>>>(l2, f1w, f1b, hbuf, 512, 128, 1.0f, 2, nullptr);
    // 9. fc2 + residual -> output
    gemm_kernel<<<g128, gblk>>>(hbuf, f2w, f2b, outp, 128, 512, 1.0f, 3, xr);
}

// round 2
// speedup vs baseline: 2.0260x; 2.0260x over previous
#include <cuda_runtime.h>
#include <math.h>

#define MTOK 262144   // B*H*W = 4*256*256
#define CDIM 128
#define HID  512

// ---------------- scratch (device globals: allocation-free) ----------------
__device__ float g_xw[(size_t)MTOK*CDIM];  // LN1 + shifted window-partitioned tokens
__device__ float g_q [(size_t)MTOK*CDIM];
__device__ float g_k [(size_t)MTOK*CDIM];
__device__ float g_v [(size_t)MTOK*CDIM];
__device__ float g_ao[(size_t)MTOK*CDIM];  // attention output (window order)
__device__ float g_xr[(size_t)MTOK*CDIM];  // shortcut + proj (original order)
__device__ float g_l2[(size_t)MTOK*CDIM];  // LN2 output
__device__ float g_h [(size_t)MTOK*HID];   // gelu(fc1)

__device__ __forceinline__ int region(int a) { return a < 248 ? 0 : (a < 252 ? 1 : 2); }

__device__ __forceinline__ unsigned f2tf(float f) {
    unsigned u; asm("cvt.rna.tf32.f32 %0, %1;" : "=r"(u) : "f"(f)); return u;
}
__device__ __forceinline__ void mma_tf32(float c[4], const unsigned a[4], const unsigned b[2]) {
    asm volatile("mma.sync.aligned.m16n8k8.row.col.f32.tf32.tf32.f32 "
        "{%0,%1,%2,%3}, {%4,%5,%6,%7}, {%8,%9}, {%0,%1,%2,%3};\n"
        : "+f"(c[0]), "+f"(c[1]), "+f"(c[2]), "+f"(c[3])
        : "r"(a[0]), "r"(a[1]), "r"(a[2]), "r"(a[3]), "r"(b[0]), "r"(b[1]));
}

// ---------------- LayerNorm (optionally fused with shift+window gather) ----
__global__ void ln_kernel(const float* __restrict__ in, const float* __restrict__ gamma,
                          const float* __restrict__ beta, float* __restrict__ out, int gather)
{
    int token = blockIdx.x * 8 + (threadIdx.x >> 5);
    int lane  = threadIdx.x & 31;
    int src = token;
    if (gather) {
        int b = token >> 16, w = (token >> 6) & 1023, t = token & 63;
        int wh = w >> 5, ww = w & 31, ti = t >> 3, tj = t & 7;
        int r = (wh*8 + ti + 4) & 255;
        int c = (ww*8 + tj + 4) & 255;
        src = (b << 16) | (r << 8) | c;
    }
    float4 xv = ((const float4*)in)[(size_t)src*32 + lane];
    float s  = xv.x + xv.y + xv.z + xv.w;
    float sq = xv.x*xv.x + xv.y*xv.y + xv.z*xv.z + xv.w*xv.w;
    #pragma unroll
    for (int o = 16; o; o >>= 1) {
        s  += __shfl_xor_sync(0xffffffffu, s,  o);
        sq += __shfl_xor_sync(0xffffffffu, sq, o);
    }
    float mean = s * (1.f/128.f);
    float var  = sq * (1.f/128.f) - mean*mean;
    float rstd = rsqrtf(var + 1e-5f);
    float4 g  = ((const float4*)gamma)[lane];
    float4 bt = ((const float4*)beta)[lane];
    float4 ov;
    ov.x = (xv.x - mean)*rstd*g.x + bt.x;
    ov.y = (xv.y - mean)*rstd*g.y + bt.y;
    ov.z = (xv.z - mean)*rstd*g.z + bt.z;
    ov.w = (xv.w - mean)*rstd*g.w + bt.w;
    ((float4*)out)[(size_t)token*32 + lane] = ov;
}

// ---------------- tf32 tensor-core GEMM: C[M,N] = A[M,K] @ B[K,N] ----------
// Tile: BM=128, BN=64, BK=16. 256 threads = 8 warps (2m x 4n), warptile 64x16.
// modes: 0: (acc+bias)*scale   1: proj+perm+shortcut   2: gelu   3: +add residual
#define BM 128
#define BN 64
#define BK 16
#define ASTR 20   // As row stride (pad): bank (4r+k)%32 bijective on frag
#define BSTR 72   // Bs row stride (pad): bank (8k+n)%32 bijective on frag

__global__ void __launch_bounds__(256) gemm_tc(
    const float* __restrict__ A, const float* __restrict__ Bw,
    const float* __restrict__ bias, float* __restrict__ Cout,
    int N, int K, float scale, int mode, const float* __restrict__ add)
{
    __shared__ unsigned As[2][BM*ASTR];
    __shared__ unsigned Bs[2][BK*BSTR];

    const int tid  = threadIdx.x;
    const int lane = tid & 31;
    const int lr   = lane >> 2;      // group id
    const int lc   = lane & 3;       // thread in group
    const int w    = tid >> 5;
    const int wm   = w >> 2;         // 0..1
    const int wn   = w & 3;          // 0..3
    const int m0   = blockIdx.y * BM;
    const int n0   = blockIdx.x * BN;

    // global load coordinates (fixed per thread)
    const int arow0 = tid >> 2;                 // rows 0..63
    const int ac4   = (tid & 3) << 2;
    const int brow  = tid >> 4;                 // 0..15
    const int bc4   = (tid & 15) << 2;

    const float* Ap0 = A + (size_t)(m0 + arow0)      * K + ac4;
    const float* Ap1 = A + (size_t)(m0 + arow0 + 64) * K + ac4;
    const float* Bp  = Bw + (size_t)brow * N + n0 + bc4;

    float4 ar0, ar1, br0;
    const int stages = K >> 4;

    // prologue: tile 0
    ar0 = *(const float4*)(Ap0);
    ar1 = *(const float4*)(Ap1);
    br0 = *(const float4*)(Bp);
    {
        uint4 u0 = make_uint4(f2tf(ar0.x), f2tf(ar0.y), f2tf(ar0.z), f2tf(ar0.w));
        uint4 u1 = make_uint4(f2tf(ar1.x), f2tf(ar1.y), f2tf(ar1.z), f2tf(ar1.w));
        uint4 ub = make_uint4(f2tf(br0.x), f2tf(br0.y), f2tf(br0.z), f2tf(br0.w));
        *(uint4*)&As[0][arow0*ASTR + ac4]      = u0;
        *(uint4*)&As[0][(arow0+64)*ASTR + ac4] = u1;
        *(uint4*)&Bs[0][brow*BSTR + bc4]       = ub;
    }
    __syncthreads();

    float acc[4][2][4];
    #pragma unroll
    for (int i = 0; i < 4; i++)
        #pragma unroll
        for (int j = 0; j < 2; j++)
            #pragma unroll
            for (int c = 0; c < 4; c++) acc[i][j][c] = 0.f;

    for (int t = 0; t < stages; t++) {
        const int cur = t & 1;
        if (t + 1 < stages) {
            int kt = (t + 1) << 4;
            ar0 = *(const float4*)(Ap0 + kt);
            ar1 = *(const float4*)(Ap1 + kt);
            br0 = *(const float4*)(Bp + (size_t)kt * N);
        }
        const unsigned* as = As[cur];
        const unsigned* bs = Bs[cur];
        #pragma unroll
        for (int kk = 0; kk < BK; kk += 8) {
            unsigned afr[4][4], bfr[2][2];
            #pragma unroll
            for (int i = 0; i < 4; i++) {
                int base = (wm*64 + i*16 + lr)*ASTR + kk + lc;
                afr[i][0] = as[base];
                afr[i][1] = as[base + 8*ASTR];
                afr[i][2] = as[base + 4];
                afr[i][3] = as[base + 8*ASTR + 4];
            }
            #pragma unroll
            for (int j = 0; j < 2; j++) {
                int nb = wn*16 + j*8 + lr;
                bfr[j][0] = bs[(kk + lc)*BSTR + nb];
                bfr[j][1] = bs[(kk + lc + 4)*BSTR + nb];
            }
            #pragma unroll
            for (int i = 0; i < 4; i++)
                #pragma unroll
                for (int j = 0; j < 2; j++)
                    mma_tf32(acc[i][j], afr[i], bfr[j]);
        }
        if (t + 1 < stages) {
            const int nxt = (t + 1) & 1;
            uint4 u0 = make_uint4(f2tf(ar0.x), f2tf(ar0.y), f2tf(ar0.z), f2tf(ar0.w));
            uint4 u1 = make_uint4(f2tf(ar1.x), f2tf(ar1.y), f2tf(ar1.z), f2tf(ar1.w));
            uint4 ub = make_uint4(f2tf(br0.x), f2tf(br0.y), f2tf(br0.z), f2tf(br0.w));
            *(uint4*)&As[nxt][arow0*ASTR + ac4]      = u0;
            *(uint4*)&As[nxt][(arow0+64)*ASTR + ac4] = u1;
            *(uint4*)&Bs[nxt][brow*BSTR + bc4]       = ub;
            __syncthreads();
        }
    }

    // epilogue
    #pragma unroll
    for (int i = 0; i < 4; i++) {
        #pragma unroll
        for (int half = 0; half < 2; half++) {
            int m = m0 + wm*64 + i*16 + lr + half*8;
            size_t dstrow;
            if (mode == 1) {
                int b = m >> 16, ww_ = (m >> 6) & 1023, tt = m & 63;
                int wh = ww_ >> 5, wwc = ww_ & 31, ti = tt >> 3, tj = tt & 7;
                int rr = (wh*8 + ti + 4) & 255;
                int cc = (wwc*8 + tj + 4) & 255;
                dstrow = (size_t)((b << 16) | (rr << 8) | cc) * N;
            } else {
                dstrow = (size_t)m * N;
            }
            #pragma unroll
            for (int j = 0; j < 2; j++) {
                int n = n0 + wn*16 + j*8 + 2*lc;
                float v0 = acc[i][j][half*2 + 0] + bias[n];
                float v1 = acc[i][j][half*2 + 1] + bias[n+1];
                if (mode == 0) { v0 *= scale; v1 *= scale; }
                else if (mode == 2) {
                    v0 = 0.5f*v0*(1.0f + erff(v0*0.70710678118654752f));
                    v1 = 0.5f*v1*(1.0f + erff(v1*0.70710678118654752f));
                } else {
                    v0 += add[dstrow + n];
                    v1 += add[dstrow + n + 1];
                }
                *(float2*)&Cout[dstrow + n] = make_float2(v0, v1);
            }
        }
    }
}

// ---------------- windowed attention via tensor cores ----------------------
// One block per (window, head), 64 threads = 2 warps.
// S = Q(64x32) @ K^T  via mma (warps split n-halves), softmax per-thread-row,
// P @ V via mma (warps split m-halves). 1/sum folded into epilogue.
__global__ void __launch_bounds__(64) attn_kernel(
    const float* __restrict__ q, const float* __restrict__ k,
    const float* __restrict__ v, const float* __restrict__ rpb,
    float* __restrict__ out)
{
    __shared__ unsigned Qs[64*36];   // (4r+k)%32 bijective for a-frag
    __shared__ unsigned Ks[64*36];   // (4n+k)%32 bijective for b-frag
    __shared__ unsigned Vs[64*40];   // (8k+n)%32 bijective for b-frag
    __shared__ unsigned Ps[64*68];   // scores then tf32 probs; (4r+k)%32 ok for a-frag
    __shared__ float    invs[64];

    const int win  = blockIdx.x >> 2;
    const int head = blockIdx.x & 3;
    const int tid  = threadIdx.x;       // 0..63
    const int lane = tid & 31;
    const int lr   = lane >> 2;
    const int lc   = lane & 3;
    const int w    = tid >> 5;          // warp 0/1
    const int wloc = win & 1023;
    const int wh = wloc >> 5, ww = wloc & 31;

    const size_t rowbase = ((size_t)win*64 + tid)*128 + head*32;

    // load q/k/v rows (token tid) as tf32
    #pragma unroll
    for (int d4 = 0; d4 < 8; d4++) {
        float4 qv = *(const float4*)(q + rowbase + d4*4);
        float4 kv = *(const float4*)(k + rowbase + d4*4);
        float4 vv = *(const float4*)(v + rowbase + d4*4);
        *(uint4*)&Qs[tid*36 + d4*4] = make_uint4(f2tf(qv.x), f2tf(qv.y), f2tf(qv.z), f2tf(qv.w));
        *(uint4*)&Ks[tid*36 + d4*4] = make_uint4(f2tf(kv.x), f2tf(kv.y), f2tf(kv.z), f2tf(kv.w));
        *(uint4*)&Vs[tid*40 + d4*4] = make_uint4(f2tf(vv.x), f2tf(vv.y), f2tf(vv.z), f2tf(vv.w));
    }
    __syncthreads();

    // ---- S = Q @ K^T : warp w covers key-cols [w*32, w*32+32) ----
    {
        float s[4][4][4];
        #pragma unroll
        for (int i = 0; i < 4; i++)
            #pragma unroll
            for (int j = 0; j < 4; j++)
                #pragma unroll
                for (int c = 0; c < 4; c++) s[i][j][c] = 0.f;

        const int nb0 = w*32;
        #pragma unroll
        for (int kk = 0; kk < 32; kk += 8) {
            unsigned afr[4][4], bfr[4][2];
            #pragma unroll
            for (int i = 0; i < 4; i++) {
                int base = (i*16 + lr)*36 + kk + lc;
                afr[i][0] = Qs[base];
                afr[i][1] = Qs[base + 8*36];
                afr[i][2] = Qs[base + 4];
                afr[i][3] = Qs[base + 8*36 + 4];
            }
            #pragma unroll
            for (int j = 0; j < 4; j++) {
                int nn = nb0 + j*8 + lr;
                bfr[j][0] = Ks[nn*36 + kk + lc];
                bfr[j][1] = Ks[nn*36 + kk + lc + 4];
            }
            #pragma unroll
            for (int i = 0; i < 4; i++)
                #pragma unroll
                for (int j = 0; j < 4; j++)
                    mma_tf32(s[i][j], afr[i], bfr[j]);
        }
        // store raw scores (float bits) into Ps
        #pragma unroll
        for (int i = 0; i < 4; i++)
            #pragma unroll
            for (int j = 0; j < 4; j++) {
                int row = i*16 + lr;
                int col = nb0 + j*8 + 2*lc;
                Ps[row*68 + col]          = __float_as_uint(s[i][j][0]);
                Ps[row*68 + col + 1]      = __float_as_uint(s[i][j][1]);
                Ps[(row+8)*68 + col]      = __float_as_uint(s[i][j][2]);
                Ps[(row+8)*68 + col + 1]  = __float_as_uint(s[i][j][3]);
            }
    }
    __syncthreads();

    // ---- softmax: thread tid handles query row tid ----
    {
        const int ti = tid >> 3, tj = tid & 7;
        const int myl = 3*region(wh*8 + ti) + region(ww*8 + tj);
        float mx = -1e30f;
        #pragma unroll 8
        for (int j = 0; j < 64; j++) {
            int ki = j >> 3, kj = j & 7;
            float sc = __uint_as_float(Ps[tid*68 + j]);
            sc += rpb[((ti - ki + 7)*15 + (tj - kj + 7))*4 + head];
            int jl = 3*region(wh*8 + ki) + region(ww*8 + kj);
            if (jl != myl) sc -= 100.f;
            Ps[tid*68 + j] = __float_as_uint(sc);
            mx = fmaxf(mx, sc);
        }
        float sum = 0.f;
        #pragma unroll 8
        for (int j = 0; j < 64; j++) {
            float e = __expf(__uint_as_float(Ps[tid*68 + j]) - mx);
            sum += e;
            Ps[tid*68 + j] = f2tf(e);
        }
        invs[tid] = 1.f / sum;
    }
    __syncthreads();

    // ---- O = P @ V : warp w covers query rows [w*32, w*32+32) ----
    {
        float o[2][4][4];
        #pragma unroll
        for (int i = 0; i < 2; i++)
            #pragma unroll
            for (int j = 0; j < 4; j++)
                #pragma unroll
                for (int c = 0; c < 4; c++) o[i][j][c] = 0.f;

        const int mb = w*32;
        #pragma unroll
        for (int kk = 0; kk < 64; kk += 8) {
            unsigned afr[2][4], bfr[4][2];
            #pragma unroll
            for (int i = 0; i < 2; i++) {
                int base = (mb + i*16 + lr)*68 + kk + lc;
                afr[i][0] = Ps[base];
                afr[i][1] = Ps[base + 8*68];
                afr[i][2] = Ps[base + 4];
                afr[i][3] = Ps[base + 8*68 + 4];
            }
            #pragma unroll
            for (int j = 0; j < 4; j++) {
                int nn = j*8 + lr;
                bfr[j][0] = Vs[(kk + lc)*40 + nn];
                bfr[j][1] = Vs[(kk + lc + 4)*40 + nn];
            }
            #pragma unroll
            for (int i = 0; i < 2; i++)
                #pragma unroll
                for (int j = 0; j < 4; j++)
                    mma_tf32(o[i][j], afr[i], bfr[j]);
        }
        #pragma unroll
        for (int i = 0; i < 2; i++) {
            #pragma unroll
            for (int half = 0; half < 2; half++) {
                int row = mb + i*16 + lr + half*8;
                float inv = invs[row];
                size_t ob = ((size_t)win*64 + row)*128 + head*32;
                #pragma unroll
                for (int j = 0; j < 4; j++) {
                    int col = j*8 + 2*lc;
                    float v0 = o[i][j][half*2 + 0] * inv;
                    float v1 = o[i][j][half*2 + 1] * inv;
                    *(float2*)&out[ob + col] = make_float2(v0, v1);
                }
            }
        }
    }
}

// ---------------------------------------------------------------------------
extern "C" void kernel_launch(void* const* d_in, const int* in_sizes, int n_in,
                              void* d_out, int out_size)
{
    const float* hs   = (const float*)d_in[0];
    const float* l1s  = (const float*)d_in[1];
    const float* l1b  = (const float*)d_in[2];
    const float* qw   = (const float*)d_in[3];
    const float* qb   = (const float*)d_in[4];
    const float* kw   = (const float*)d_in[5];
    const float* kb   = (const float*)d_in[6];
    const float* vw   = (const float*)d_in[7];
    const float* vb   = (const float*)d_in[8];
    const float* pw   = (const float*)d_in[9];
    const float* pb   = (const float*)d_in[10];
    const float* rpb  = (const float*)d_in[11];
    const float* l2s  = (const float*)d_in[12];
    const float* l2b  = (const float*)d_in[13];
    const float* f1w  = (const float*)d_in[14];
    const float* f1b  = (const float*)d_in[15];
    const float* f2w  = (const float*)d_in[16];
    const float* f2b  = (const float*)d_in[17];
    float* outp = (float*)d_out;

    float *xw, *qx, *kx, *vx, *ao, *xr, *l2, *hbuf;
    cudaGetSymbolAddress((void**)&xw,   g_xw);
    cudaGetSymbolAddress((void**)&qx,   g_q);
    cudaGetSymbolAddress((void**)&kx,   g_k);
    cudaGetSymbolAddress((void**)&vx,   g_v);
    cudaGetSymbolAddress((void**)&ao,   g_ao);
    cudaGetSymbolAddress((void**)&xr,   g_xr);
    cudaGetSymbolAddress((void**)&l2,   g_l2);
    cudaGetSymbolAddress((void**)&hbuf, g_h);

    const float qscale = 0.17677669529663687f;  // 1/sqrt(32)
    dim3 g128(128/BN, MTOK/BM);   // (2, 2048)
    dim3 g512(512/BN, MTOK/BM);   // (8, 2048)

    // 1. LN1 + shift + window partition
    ln_kernel<<<MTOK/8, 256>>>(hs, l1s, l1b, xw, 1);
    // 2-4. Q, K, V projections (Q scaled)
    gemm_tc<<<g128, 256>>>(xw, qw, qb, qx, 128, 128, qscale, 0, nullptr);
    gemm_tc<<<g128, 256>>>(xw, kw, kb, kx, 128, 128, 1.0f,   0, nullptr);
    gemm_tc<<<g128, 256>>>(xw, vw, vb, vx, 128, 128, 1.0f,   0, nullptr);
    // 5. windowed attention (tensor cores)
    attn_kernel<<<4096*4, 64>>>(qx, kx, vx, rpb, ao);
    // 6. proj + window-reverse/unshift + shortcut add
    gemm_tc<<<g128, 256>>>(ao, pw, pb, xr, 128, 128, 1.0f, 1, hs);
    // 7. LN2
    ln_kernel<<<MTOK/8, 256>>>(xr, l2s, l2b, l2, 0);
    // 8. fc1 + GELU
    gemm_tc<<<g512, 256>>>(l2, f1w, f1b, hbuf, 512, 128, 1.0f, 2, nullptr);
    // 9. fc2 + residual -> output
    gemm_tc<<<g128, 256>>>(hbuf, f2w, f2b, outp, 128, 512, 1.0f, 3, xr);
}

// round 3
// speedup vs baseline: 2.4047x; 1.1869x over previous
#include <cuda_runtime.h>
#include <math.h>

#define MTOK 262144   // B*H*W = 4*256*256
#define CDIM 128
#define HID  512

// ---------------- scratch (device globals: allocation-free) ----------------
__device__ float g_xw[(size_t)MTOK*CDIM];  // LN1 + shifted window-partitioned tokens
__device__ float g_q [(size_t)MTOK*CDIM];
__device__ float g_k [(size_t)MTOK*CDIM];
__device__ float g_v [(size_t)MTOK*CDIM];
__device__ float g_ao[(size_t)MTOK*CDIM];  // attention output (window order)
__device__ float g_xr[(size_t)MTOK*CDIM];  // x = shortcut + proj (WINDOW order)
__device__ float g_l2[(size_t)MTOK*CDIM];  // LN2(x) (window order)
__device__ float g_h [(size_t)MTOK*HID];   // gelu(fc1) (window order)

__device__ __forceinline__ int region(int a) { return a < 248 ? 0 : (a < 252 ? 1 : 2); }

__device__ __forceinline__ unsigned f2tf(float f) {
    unsigned u; asm("cvt.rna.tf32.f32 %0, %1;" : "=r"(u) : "f"(f)); return u;
}
__device__ __forceinline__ void mma_tf32(float c[4], const unsigned a[4], const unsigned b[2]) {
    asm volatile("mma.sync.aligned.m16n8k8.row.col.f32.tf32.tf32.f32 "
        "{%0,%1,%2,%3}, {%4,%5,%6,%7}, {%8,%9}, {%0,%1,%2,%3};\n"
        : "+f"(c[0]), "+f"(c[1]), "+f"(c[2]), "+f"(c[3])
        : "r"(a[0]), "r"(a[1]), "r"(a[2]), "r"(a[3]), "r"(b[0]), "r"(b[1]));
}
// window-order index m -> original token index (window reverse + roll(+4,+4))
__device__ __forceinline__ int perm_m(int m) {
    int b = m >> 16, w = (m >> 6) & 1023, t = m & 63;
    int wh = w >> 5, ww = w & 31, ti = t >> 3, tj = t & 7;
    int r = (wh*8 + ti + 4) & 255;
    int c = (ww*8 + tj + 4) & 255;
    return (b << 16) | (r << 8) | c;
}

// ---------------- LayerNorm (fused with shift+window gather) ---------------
__global__ void ln_kernel(const float* __restrict__ in, const float* __restrict__ gamma,
                          const float* __restrict__ beta, float* __restrict__ out, int gather)
{
    int token = blockIdx.x * 8 + (threadIdx.x >> 5);
    int lane  = threadIdx.x & 31;
    int src = gather ? perm_m(token) : token;
    float4 xv = ((const float4*)in)[(size_t)src*32 + lane];
    float s  = xv.x + xv.y + xv.z + xv.w;
    float sq = xv.x*xv.x + xv.y*xv.y + xv.z*xv.z + xv.w*xv.w;
    #pragma unroll
    for (int o = 16; o; o >>= 1) {
        s  += __shfl_xor_sync(0xffffffffu, s,  o);
        sq += __shfl_xor_sync(0xffffffffu, sq, o);
    }
    float mean = s * (1.f/128.f);
    float var  = sq * (1.f/128.f) - mean*mean;
    float rstd = rsqrtf(var + 1e-5f);
    float4 g  = ((const float4*)gamma)[lane];
    float4 bt = ((const float4*)beta)[lane];
    float4 ov;
    ov.x = (xv.x - mean)*rstd*g.x + bt.x;
    ov.y = (xv.y - mean)*rstd*g.y + bt.y;
    ov.z = (xv.z - mean)*rstd*g.z + bt.z;
    ov.w = (xv.w - mean)*rstd*g.w + bt.w;
    ((float4*)out)[(size_t)token*32 + lane] = ov;
}

// ---------------- tf32 tensor-core GEMM: C[M,N] = A[M,K] @ B[K,N] ----------
// BM=128, BN=128, BK=16. 128 threads = 4 warps (2m x 2n), warptile 64x64.
// modes: 0: fused QKV (blockIdx.x selects W/bias/out; scale on x==0)
//        1: proj: x = acc+bias+hs[perm(m)]; write x -> C0, LN2(x) -> ln_out
//        2: gelu(acc+bias)
//        3: fc2: C0[perm(m)] = acc + bias + add[m]
#define BM 128
#define BN 128
#define BK 16
#define ASTR 20    // (16i+lr)*20+lc distinct mod 32 -> conflict-free a-frag reads
#define BSTR 136   // 136 % 32 == 8 -> 8*lc + 8*j + lr distinct -> conflict-free b reads

__global__ void __launch_bounds__(128) gemm_tc(
    const float* __restrict__ A,
    const float* __restrict__ W0, const float* __restrict__ B0, float* __restrict__ C0,
    const float* __restrict__ W1, const float* __restrict__ B1, float* __restrict__ C1,
    const float* __restrict__ W2, const float* __restrict__ B2, float* __restrict__ C2,
    int N, int K, float scale, int mode,
    const float* __restrict__ add, float* __restrict__ ln_out,
    const float* __restrict__ gamma, const float* __restrict__ beta)
{
    __shared__ unsigned As[2][BM*ASTR];
    __shared__ unsigned Bs[2][BK*BSTR];
    __shared__ float red_s[BM][2];
    __shared__ float red_q[BM][2];

    const int tid  = threadIdx.x;
    const int lane = tid & 31;
    const int lr   = lane >> 2;
    const int lc   = lane & 3;
    const int w    = tid >> 5;
    const int wm   = w >> 1;         // 0..1
    const int wn   = w & 1;          // 0..1
    const int m0   = blockIdx.y * BM;

    const float* Bw; const float* bias; float* Cout; float sc; int n0;
    if (mode == 0) {
        int s = blockIdx.x;
        Bw   = s == 0 ? W0 : (s == 1 ? W1 : W2);
        bias = s == 0 ? B0 : (s == 1 ? B1 : B2);
        Cout = s == 0 ? C0 : (s == 1 ? C1 : C2);
        sc   = s == 0 ? scale : 1.0f;
        n0   = 0;
    } else {
        Bw = W0; bias = B0; Cout = C0; sc = 1.0f;
        n0 = blockIdx.x * BN;
    }

    // global load coords
    const int arow = tid >> 2;            // 0..31 (+32*i)
    const int ac4  = (tid & 3) << 2;      // 0,4,8,12
    const int brow = tid >> 5;            // 0..3  (+4*i)
    const int bc4  = (tid & 31) << 2;     // 0..124

    const float* ApB = A  + (size_t)(m0 + arow) * K + ac4;
    const float* BpB = Bw + (size_t)brow * N + n0 + bc4;

    float4 areg[4], breg[4];
    const int stages = K >> 4;

    // prologue
    #pragma unroll
    for (int i = 0; i < 4; i++) {
        areg[i] = *(const float4*)(ApB + (size_t)(32*i)*K);
        breg[i] = *(const float4*)(BpB + (size_t)(4*i)*N);
    }
    #pragma unroll
    for (int i = 0; i < 4; i++) {
        *(uint4*)&As[0][(arow + 32*i)*ASTR + ac4] =
            make_uint4(f2tf(areg[i].x), f2tf(areg[i].y), f2tf(areg[i].z), f2tf(areg[i].w));
        *(uint4*)&Bs[0][(brow + 4*i)*BSTR + bc4] =
            make_uint4(f2tf(breg[i].x), f2tf(breg[i].y), f2tf(breg[i].z), f2tf(breg[i].w));
    }
    __syncthreads();

    float acc[4][8][4];
    #pragma unroll
    for (int i = 0; i < 4; i++)
        #pragma unroll
        for (int j = 0; j < 8; j++)
            #pragma unroll
            for (int c = 0; c < 4; c++) acc[i][j][c] = 0.f;

    for (int t = 0; t < stages; t++) {
        const int cur = t & 1;
        if (t + 1 < stages) {
            int kt = (t + 1) << 4;
            #pragma unroll
            for (int i = 0; i < 4; i++) {
                areg[i] = *(const float4*)(ApB + (size_t)(32*i)*K + kt);
                breg[i] = *(const float4*)(BpB + (size_t)(kt + 4*i)*N);
            }
        }
        const unsigned* as = As[cur];
        const unsigned* bs = Bs[cur];
        #pragma unroll
        for (int kk = 0; kk < BK; kk += 8) {
            unsigned afr[4][4];
            #pragma unroll
            for (int i = 0; i < 4; i++) {
                int base = (wm*64 + i*16 + lr)*ASTR + kk + lc;
                afr[i][0] = as[base];
                afr[i][1] = as[base + 8*ASTR];
                afr[i][2] = as[base + 4];
                afr[i][3] = as[base + 8*ASTR + 4];
            }
            #pragma unroll
            for (int j = 0; j < 8; j++) {
                unsigned bfr[2];
                int nb = wn*64 + j*8 + lr;
                bfr[0] = bs[(kk + lc)*BSTR + nb];
                bfr[1] = bs[(kk + lc + 4)*BSTR + nb];
                #pragma unroll
                for (int i = 0; i < 4; i++)
                    mma_tf32(acc[i][j], afr[i], bfr);
            }
        }
        if (t + 1 < stages) {
            const int nxt = (t + 1) & 1;
            #pragma unroll
            for (int i = 0; i < 4; i++) {
                *(uint4*)&As[nxt][(arow + 32*i)*ASTR + ac4] =
                    make_uint4(f2tf(areg[i].x), f2tf(areg[i].y), f2tf(areg[i].z), f2tf(areg[i].w));
                *(uint4*)&Bs[nxt][(brow + 4*i)*BSTR + bc4] =
                    make_uint4(f2tf(breg[i].x), f2tf(breg[i].y), f2tf(breg[i].z), f2tf(breg[i].w));
            }
            __syncthreads();
        }
    }

    // ---------------- epilogue ----------------
    if (mode == 1) {
        // x = acc + bias + hs[perm(m)]; row stats for LN2
        #pragma unroll
        for (int i = 0; i < 4; i++) {
            #pragma unroll
            for (int half = 0; half < 2; half++) {
                int rl = wm*64 + i*16 + lr + half*8;       // local row 0..127
                int m  = m0 + rl;
                const float* hsrow = add + (size_t)perm_m(m) * 128;
                float s = 0.f, sq = 0.f;
                #pragma unroll
                for (int j = 0; j < 8; j++) {
                    int n = wn*64 + j*8 + 2*lc;
                    float v0 = acc[i][j][half*2 + 0] + bias[n]   + hsrow[n];
                    float v1 = acc[i][j][half*2 + 1] + bias[n+1] + hsrow[n+1];
                    acc[i][j][half*2 + 0] = v0;
                    acc[i][j][half*2 + 1] = v1;
                    s  += v0 + v1;
                    sq += v0*v0 + v1*v1;
                }
                s  += __shfl_xor_sync(0xffffffffu, s, 1);
                s  += __shfl_xor_sync(0xffffffffu, s, 2);
                sq += __shfl_xor_sync(0xffffffffu, sq, 1);
                sq += __shfl_xor_sync(0xffffffffu, sq, 2);
                if (lc == 0) { red_s[rl][wn] = s; red_q[rl][wn] = sq; }
            }
        }
        __syncthreads();
        #pragma unroll
        for (int i = 0; i < 4; i++) {
            #pragma unroll
            for (int half = 0; half < 2; half++) {
                int rl = wm*64 + i*16 + lr + half*8;
                float s  = red_s[rl][0] + red_s[rl][1];
                float sq = red_q[rl][0] + red_q[rl][1];
                float mu = s * (1.f/128.f);
                float var = sq * (1.f/128.f) - mu*mu;
                float rstd = rsqrtf(var + 1e-5f);
                size_t base = (size_t)(m0 + rl) * 128;
                #pragma unroll
                for (int j = 0; j < 8; j++) {
                    int n = wn*64 + j*8 + 2*lc;
                    float v0 = acc[i][j][half*2 + 0];
                    float v1 = acc[i][j][half*2 + 1];
                    *(float2*)&Cout[base + n] = make_float2(v0, v1);
                    float l0 = (v0 - mu)*rstd*gamma[n]   + beta[n];
                    float l1 = (v1 - mu)*rstd*gamma[n+1] + beta[n+1];
                    *(float2*)&ln_out[base + n] = make_float2(l0, l1);
                }
            }
        }
    } else {
        #pragma unroll
        for (int i = 0; i < 4; i++) {
            #pragma unroll
            for (int half = 0; half < 2; half++) {
                int m = m0 + wm*64 + i*16 + lr + half*8;
                size_t dstrow = (mode == 3) ? (size_t)perm_m(m) * 128 : (size_t)m * N;
                const float* addrow = (mode == 3) ? add + (size_t)m * 128 : nullptr;
                #pragma unroll
                for (int j = 0; j < 8; j++) {
                    int n = wn*64 + j*8 + 2*lc;
                    int ng = n0 + n;
                    float v0 = acc[i][j][half*2 + 0] + bias[ng];
                    float v1 = acc[i][j][half*2 + 1] + bias[ng+1];
                    if (mode == 0) { v0 *= sc; v1 *= sc; }
                    else if (mode == 2) {
                        v0 = 0.5f*v0*(1.0f + erff(v0*0.70710678118654752f));
                        v1 = 0.5f*v1*(1.0f + erff(v1*0.70710678118654752f));
                    } else {
                        v0 += addrow[n];
                        v1 += addrow[n+1];
                    }
                    *(float2*)&Cout[dstrow + ng] = make_float2(v0, v1);
                }
            }
        }
    }
}

// ---------------- windowed attention via tensor cores ----------------------
__global__ void __launch_bounds__(64) attn_kernel(
    const float* __restrict__ q, const float* __restrict__ k,
    const float* __restrict__ v, const float* __restrict__ rpb,
    float* __restrict__ out)
{
    __shared__ unsigned Qs[64*36];
    __shared__ unsigned Ks[64*36];
    __shared__ unsigned Vs[64*40];
    __shared__ unsigned Ps[64*68];
    __shared__ float    invs[64];

    const int win  = blockIdx.x >> 2;
    const int head = blockIdx.x & 3;
    const int tid  = threadIdx.x;
    const int lane = tid & 31;
    const int lr   = lane >> 2;
    const int lc   = lane & 3;
    const int w    = tid >> 5;
    const int wloc = win & 1023;
    const int wh = wloc >> 5, ww = wloc & 31;

    const size_t rowbase = ((size_t)win*64 + tid)*128 + head*32;

    #pragma unroll
    for (int d4 = 0; d4 < 8; d4++) {
        float4 qv = *(const float4*)(q + rowbase + d4*4);
        float4 kv = *(const float4*)(k + rowbase + d4*4);
        float4 vv = *(const float4*)(v + rowbase + d4*4);
        *(uint4*)&Qs[tid*36 + d4*4] = make_uint4(f2tf(qv.x), f2tf(qv.y), f2tf(qv.z), f2tf(qv.w));
        *(uint4*)&Ks[tid*36 + d4*4] = make_uint4(f2tf(kv.x), f2tf(kv.y), f2tf(kv.z), f2tf(kv.w));
        *(uint4*)&Vs[tid*40 + d4*4] = make_uint4(f2tf(vv.x), f2tf(vv.y), f2tf(vv.z), f2tf(vv.w));
    }
    __syncthreads();

    // S = Q @ K^T : warp w covers key-cols [w*32, w*32+32)
    {
        float s[4][4][4];
        #pragma unroll
        for (int i = 0; i < 4; i++)
            #pragma unroll
            for (int j = 0; j < 4; j++)
                #pragma unroll
                for (int c = 0; c < 4; c++) s[i][j][c] = 0.f;

        const int nb0 = w*32;
        #pragma unroll
        for (int kk = 0; kk < 32; kk += 8) {
            unsigned afr[4][4], bfr[4][2];
            #pragma unroll
            for (int i = 0; i < 4; i++) {
                int base = (i*16 + lr)*36 + kk + lc;
                afr[i][0] = Qs[base];
                afr[i][1] = Qs[base + 8*36];
                afr[i][2] = Qs[base + 4];
                afr[i][3] = Qs[base + 8*36 + 4];
            }
            #pragma unroll
            for (int j = 0; j < 4; j++) {
                int nn = nb0 + j*8 + lr;
                bfr[j][0] = Ks[nn*36 + kk + lc];
                bfr[j][1] = Ks[nn*36 + kk + lc + 4];
            }
            #pragma unroll
            for (int i = 0; i < 4; i++)
                #pragma unroll
                for (int j = 0; j < 4; j++)
                    mma_tf32(s[i][j], afr[i], bfr[j]);
        }
        #pragma unroll
        for (int i = 0; i < 4; i++)
            #pragma unroll
            for (int j = 0; j < 4; j++) {
                int row = i*16 + lr;
                int col = nb0 + j*8 + 2*lc;
                Ps[row*68 + col]          = __float_as_uint(s[i][j][0]);
                Ps[row*68 + col + 1]      = __float_as_uint(s[i][j][1]);
                Ps[(row+8)*68 + col]      = __float_as_uint(s[i][j][2]);
                Ps[(row+8)*68 + col + 1]  = __float_as_uint(s[i][j][3]);
            }
    }
    __syncthreads();

    // softmax: thread tid = query row
    {
        const int ti = tid >> 3, tj = tid & 7;
        const int myl = 3*region(wh*8 + ti) + region(ww*8 + tj);
        float mx = -1e30f;
        #pragma unroll 8
        for (int j = 0; j < 64; j++) {
            int ki = j >> 3, kj = j & 7;
            float sc = __uint_as_float(Ps[tid*68 + j]);
            sc += rpb[((ti - ki + 7)*15 + (tj - kj + 7))*4 + head];
            int jl = 3*region(wh*8 + ki) + region(ww*8 + kj);
            if (jl != myl) sc -= 100.f;
            Ps[tid*68 + j] = __float_as_uint(sc);
            mx = fmaxf(mx, sc);
        }
        float sum = 0.f;
        #pragma unroll 8
        for (int j = 0; j < 64; j++) {
            float e = __expf(__uint_as_float(Ps[tid*68 + j]) - mx);
            sum += e;
            Ps[tid*68 + j] = f2tf(e);
        }
        invs[tid] = 1.f / sum;
    }
    __syncthreads();

    // O = P @ V : warp w covers query rows [w*32, w*32+32)
    {
        float o[2][4][4];
        #pragma unroll
        for (int i = 0; i < 2; i++)
            #pragma unroll
            for (int j = 0; j < 4; j++)
                #pragma unroll
                for (int c = 0; c < 4; c++) o[i][j][c] = 0.f;

        const int mb = w*32;
        #pragma unroll
        for (int kk = 0; kk < 64; kk += 8) {
            unsigned afr[2][4], bfr[4][2];
            #pragma unroll
            for (int i = 0; i < 2; i++) {
                int base = (mb + i*16 + lr)*68 + kk + lc;
                afr[i][0] = Ps[base];
                afr[i][1] = Ps[base + 8*68];
                afr[i][2] = Ps[base + 4];
                afr[i][3] = Ps[base + 8*68 + 4];
            }
            #pragma unroll
            for (int j = 0; j < 4; j++) {
                int nn = j*8 + lr;
                bfr[j][0] = Vs[(kk + lc)*40 + nn];
                bfr[j][1] = Vs[(kk + lc + 4)*40 + nn];
            }
            #pragma unroll
            for (int i = 0; i < 2; i++)
                #pragma unroll
                for (int j = 0; j < 4; j++)
                    mma_tf32(o[i][j], afr[i], bfr[j]);
        }
        #pragma unroll
        for (int i = 0; i < 2; i++) {
            #pragma unroll
            for (int half = 0; half < 2; half++) {
                int row = mb + i*16 + lr + half*8;
                float inv = invs[row];
                size_t ob = ((size_t)win*64 + row)*128 + head*32;
                #pragma unroll
                for (int j = 0; j < 4; j++) {
                    int col = j*8 + 2*lc;
                    float v0 = o[i][j][half*2 + 0] * inv;
                    float v1 = o[i][j][half*2 + 1] * inv;
                    *(float2*)&out[ob + col] = make_float2(v0, v1);
                }
            }
        }
    }
}

// ---------------------------------------------------------------------------
extern "C" void kernel_launch(void* const* d_in, const int* in_sizes, int n_in,
                              void* d_out, int out_size)
{
    const float* hs   = (const float*)d_in[0];
    const float* l1s  = (const float*)d_in[1];
    const float* l1b  = (const float*)d_in[2];
    const float* qw   = (const float*)d_in[3];
    const float* qb   = (const float*)d_in[4];
    const float* kw   = (const float*)d_in[5];
    const float* kb   = (const float*)d_in[6];
    const float* vw   = (const float*)d_in[7];
    const float* vb   = (const float*)d_in[8];
    const float* pw   = (const float*)d_in[9];
    const float* pb   = (const float*)d_in[10];
    const float* rpb  = (const float*)d_in[11];
    const float* l2s  = (const float*)d_in[12];
    const float* l2b  = (const float*)d_in[13];
    const float* f1w  = (const float*)d_in[14];
    const float* f1b  = (const float*)d_in[15];
    const float* f2w  = (const float*)d_in[16];
    const float* f2b  = (const float*)d_in[17];
    float* outp = (float*)d_out;

    float *xw, *qx, *kx, *vx, *ao, *xr, *l2, *hbuf;
    cudaGetSymbolAddress((void**)&xw,   g_xw);
    cudaGetSymbolAddress((void**)&qx,   g_q);
    cudaGetSymbolAddress((void**)&kx,   g_k);
    cudaGetSymbolAddress((void**)&vx,   g_v);
    cudaGetSymbolAddress((void**)&ao,   g_ao);
    cudaGetSymbolAddress((void**)&xr,   g_xr);
    cudaGetSymbolAddress((void**)&l2,   g_l2);
    cudaGetSymbolAddress((void**)&hbuf, g_h);

    const float qscale = 0.17677669529663687f;  // 1/sqrt(32)

    // 1. LN1 + shift + window partition
    ln_kernel<<<MTOK/8, 256>>>(hs, l1s, l1b, xw, 1);
    // 2. fused QKV projections (blockIdx.x selects matrix; Q scaled)
    gemm_tc<<<dim3(3, MTOK/BM), 128>>>(xw, qw, qb, qx, kw, kb, kx, vw, vb, vx,
                                       128, 128, qscale, 0, nullptr, nullptr, nullptr, nullptr);
    // 3. windowed attention (tensor cores)
    attn_kernel<<<4096*4, 64>>>(qx, kx, vx, rpb, ao);
    // 4. proj + shortcut(hs@perm) -> xr (window order), fused LN2 -> l2
    gemm_tc<<<dim3(1, MTOK/BM), 128>>>(ao, pw, pb, xr, nullptr, nullptr, nullptr, nullptr, nullptr, nullptr,
                                       128, 128, 1.0f, 1, hs, l2, l2s, l2b);
    // 5. fc1 + GELU (window order)
    gemm_tc<<<dim3(4, MTOK/BM), 128>>>(l2, f1w, f1b, hbuf, nullptr, nullptr, nullptr, nullptr, nullptr, nullptr,
                                       512, 128, 1.0f, 2, nullptr, nullptr, nullptr, nullptr);
    // 6. fc2 + residual(xr) -> out[perm(m)] (window reverse + unshift)
    gemm_tc<<<dim3(1, MTOK/BM), 128>>>(hbuf, f2w, f2b, outp, nullptr, nullptr, nullptr, nullptr, nullptr, nullptr,
                                       128, 512, 1.0f, 3, xr, nullptr, nullptr, nullptr);
}

// round 4
// speedup vs baseline: 2.5570x; 1.0633x over previous
#include <cuda_runtime.h>
#include <math.h>

#define MTOK 262144   // B*H*W = 4*256*256
#define CDIM 128
#define HID  512

// ---------------- scratch (device globals: allocation-free) ----------------
__device__ float g_xw[(size_t)MTOK*CDIM];  // LN1 + shifted window-partitioned tokens
__device__ float g_q [(size_t)MTOK*CDIM];
__device__ float g_k [(size_t)MTOK*CDIM];
__device__ float g_v [(size_t)MTOK*CDIM];
__device__ float g_ao[(size_t)MTOK*CDIM];  // attention output (window order)
__device__ float g_xr[(size_t)MTOK*CDIM];  // x = shortcut + proj (WINDOW order)
__device__ float g_l2[(size_t)MTOK*CDIM];  // LN2(x) (window order)
__device__ float g_h [(size_t)MTOK*HID];   // gelu(fc1) (window order)

__device__ __forceinline__ int region(int a) { return a < 248 ? 0 : (a < 252 ? 1 : 2); }

__device__ __forceinline__ unsigned f2tf(float f) {
    unsigned u; asm("cvt.rna.tf32.f32 %0, %1;" : "=r"(u) : "f"(f)); return u;
}
__device__ __forceinline__ unsigned u2tf(unsigned raw) {
    unsigned u; asm("cvt.rna.tf32.f32 %0, %1;" : "=r"(u) : "f"(__uint_as_float(raw))); return u;
}
__device__ __forceinline__ void mma_tf32(float c[4], const unsigned a[4], const unsigned b[2]) {
    asm volatile("mma.sync.aligned.m16n8k8.row.col.f32.tf32.tf32.f32 "
        "{%0,%1,%2,%3}, {%4,%5,%6,%7}, {%8,%9}, {%0,%1,%2,%3};\n"
        : "+f"(c[0]), "+f"(c[1]), "+f"(c[2]), "+f"(c[3])
        : "r"(a[0]), "r"(a[1]), "r"(a[2]), "r"(a[3]), "r"(b[0]), "r"(b[1]));
}
__device__ __forceinline__ void cp16(unsigned dst, const void* src) {
    asm volatile("cp.async.cg.shared.global [%0], [%1], 16;\n" :: "r"(dst), "l"(src));
}
#define CP_COMMIT asm volatile("cp.async.commit_group;\n" ::: "memory")
#define CP_WAIT1  asm volatile("cp.async.wait_group 1;\n" ::: "memory")
#define CP_WAIT0  asm volatile("cp.async.wait_group 0;\n" ::: "memory")

// window-order index m -> original token index (window reverse + roll(+4,+4))
__device__ __forceinline__ int perm_m(int m) {
    int b = m >> 16, w = (m >> 6) & 1023, t = m & 63;
    int wh = w >> 5, ww = w & 31, ti = t >> 3, tj = t & 7;
    int r = (wh*8 + ti + 4) & 255;
    int c = (ww*8 + tj + 4) & 255;
    return (b << 16) | (r << 8) | c;
}

// ---------------- LayerNorm (fused with shift+window gather) ---------------
__global__ void ln_kernel(const float* __restrict__ in, const float* __restrict__ gamma,
                          const float* __restrict__ beta, float* __restrict__ out, int gather)
{
    int token = blockIdx.x * 8 + (threadIdx.x >> 5);
    int lane  = threadIdx.x & 31;
    int src = gather ? perm_m(token) : token;
    float4 xv = ((const float4*)in)[(size_t)src*32 + lane];
    float s  = xv.x + xv.y + xv.z + xv.w;
    float sq = xv.x*xv.x + xv.y*xv.y + xv.z*xv.z + xv.w*xv.w;
    #pragma unroll
    for (int o = 16; o; o >>= 1) {
        s  += __shfl_xor_sync(0xffffffffu, s,  o);
        sq += __shfl_xor_sync(0xffffffffu, sq, o);
    }
    float mean = s * (1.f/128.f);
    float var  = sq * (1.f/128.f) - mean*mean;
    float rstd = rsqrtf(var + 1e-5f);
    float4 g  = ((const float4*)gamma)[lane];
    float4 bt = ((const float4*)beta)[lane];
    float4 ov;
    ov.x = (xv.x - mean)*rstd*g.x + bt.x;
    ov.y = (xv.y - mean)*rstd*g.y + bt.y;
    ov.z = (xv.z - mean)*rstd*g.z + bt.z;
    ov.w = (xv.w - mean)*rstd*g.w + bt.w;
    ((float4*)out)[(size_t)token*32 + lane] = ov;
}

// ---------------- tf32 tensor-core GEMM with cp.async pipeline -------------
// BM=128, BN=128, BK=16. 256 threads = 8 warps (2m x 4n), warptile 64x32.
// 3-stage cp.async double-lookahead. fp32 staged in smem; cvt->tf32 at frag load.
// modes: 0: fused QKV   1: proj + shortcut + fused LN2   2: gelu   3: fc2 + residual + perm
#define BM 128
#define BN 128
#define BK 16
#define ASTR 20
#define BSTR 136
#define NST 3
#define SA_W (BM*ASTR)          // unsigned words per A stage
#define SB_W (BK*BSTR)          // unsigned words per B stage
#define GEMM_SMEM ((NST*(SA_W + SB_W))*4 + BM*4*4*2)

__global__ void __launch_bounds__(256, 2) gemm_tc(
    const float* __restrict__ A,
    const float* __restrict__ W0, const float* __restrict__ B0, float* __restrict__ C0,
    const float* __restrict__ W1, const float* __restrict__ B1, float* __restrict__ C1,
    const float* __restrict__ W2, const float* __restrict__ B2, float* __restrict__ C2,
    int N, int K, float scale, int mode,
    const float* __restrict__ add, float* __restrict__ ln_out,
    const float* __restrict__ gamma, const float* __restrict__ beta)
{
    extern __shared__ unsigned smem[];
    unsigned* AsB = smem;                       // NST * SA_W
    unsigned* BsB = smem + NST*SA_W;            // NST * SB_W
    float* red_s = (float*)(smem + NST*(SA_W + SB_W));          // [BM][4]
    float* red_q = red_s + BM*4;                                 // [BM][4]

    const int tid  = threadIdx.x;
    const int lane = tid & 31;
    const int lr   = lane >> 2;
    const int lc   = lane & 3;
    const int w    = tid >> 5;
    const int wm   = w >> 2;         // 0..1
    const int wn   = w & 3;          // 0..3
    const int m0   = blockIdx.y * BM;

    const float* Bw; const float* bias; float* Cout; float sc; int n0;
    if (mode == 0) {
        int s = blockIdx.x;
        Bw   = s == 0 ? W0 : (s == 1 ? W1 : W2);
        bias = s == 0 ? B0 : (s == 1 ? B1 : B2);
        Cout = s == 0 ? C0 : (s == 1 ? C1 : C2);
        sc   = s == 0 ? scale : 1.0f;
        n0   = 0;
    } else {
        Bw = W0; bias = B0; Cout = C0; sc = 1.0f;
        n0 = blockIdx.x * BN;
    }

    // global src coords
    const int arow = tid >> 2;            // 0..63 (+64)
    const int ac4  = (tid & 3) << 2;
    const int brow = tid >> 5;            // 0..7  (+8)
    const int bc4  = (tid & 31) << 2;

    const float* Ap0 = A  + (size_t)(m0 + arow) * K + ac4;
    const float* Ap1 = Ap0 + (size_t)64 * K;
    const float* Bp0 = Bw + (size_t)brow * N + n0 + bc4;
    const float* Bp1 = Bp0 + (size_t)8 * N;

    // smem dst byte offsets
    const unsigned a_base = (unsigned)__cvta_generic_to_shared(AsB);
    const unsigned b_base = (unsigned)__cvta_generic_to_shared(BsB);
    const unsigned a_s0 = a_base + (arow*ASTR + ac4)*4;
    const unsigned a_s1 = a_base + ((arow+64)*ASTR + ac4)*4;
    const unsigned b_s0 = b_base + (brow*BSTR + bc4)*4;
    const unsigned b_s1 = b_base + ((brow+8)*BSTR + bc4)*4;
    const unsigned SAB = SA_W*4, SBB = SB_W*4;

    const int stages = K >> 4;

    #define ISSUE(t, buf) { \
        int kt_ = (t) << 4; \
        cp16(a_s0 + (buf)*SAB, Ap0 + kt_); \
        cp16(a_s1 + (buf)*SAB, Ap1 + kt_); \
        cp16(b_s0 + (buf)*SBB, Bp0 + (size_t)kt_ * N); \
        cp16(b_s1 + (buf)*SBB, Bp1 + (size_t)kt_ * N); \
        CP_COMMIT; }

    ISSUE(0, 0);
    ISSUE(1, 1);
    CP_WAIT1;
    __syncthreads();

    float acc[4][4][4];
    #pragma unroll
    for (int i = 0; i < 4; i++)
        #pragma unroll
        for (int j = 0; j < 4; j++)
            #pragma unroll
            for (int c = 0; c < 4; c++) acc[i][j][c] = 0.f;

    const int arow_frag = (wm*64 + lr)*ASTR + lc;    // + i*16*ASTR + kk
    const int bcol_frag = wn*32 + lr;                // + j*8

    for (int t = 0; t < stages; t++) {
        const unsigned* as = AsB + (t % NST)*SA_W;
        const unsigned* bs = BsB + (t % NST)*SB_W;
        #pragma unroll
        for (int kk = 0; kk < BK; kk += 8) {
            unsigned afr[4][4];
            #pragma unroll
            for (int i = 0; i < 4; i++) {
                int base = arow_frag + i*16*ASTR + kk;
                afr[i][0] = u2tf(as[base]);
                afr[i][1] = u2tf(as[base + 8*ASTR]);
                afr[i][2] = u2tf(as[base + 4]);
                afr[i][3] = u2tf(as[base + 8*ASTR + 4]);
            }
            #pragma unroll
            for (int j = 0; j < 4; j++) {
                unsigned bfr[2];
                int nb = bcol_frag + j*8;
                bfr[0] = u2tf(bs[(kk + lc)*BSTR + nb]);
                bfr[1] = u2tf(bs[(kk + lc + 4)*BSTR + nb]);
                #pragma unroll
                for (int i = 0; i < 4; i++)
                    mma_tf32(acc[i][j], afr[i], bfr);
            }
        }
        if (t + 2 < stages) {
            ISSUE(t + 2, (t + 2) % NST);
            CP_WAIT1;
            __syncthreads();
        } else if (t + 1 < stages) {
            CP_WAIT0;
            __syncthreads();
        }
    }
    #undef ISSUE

    // ---------------- epilogue ----------------
    if (mode == 1) {
        #pragma unroll
        for (int i = 0; i < 4; i++) {
            #pragma unroll
            for (int half = 0; half < 2; half++) {
                int rl = wm*64 + i*16 + lr + half*8;
                int m  = m0 + rl;
                const float* hsrow = add + (size_t)perm_m(m) * 128;
                float s = 0.f, sq = 0.f;
                #pragma unroll
                for (int j = 0; j < 4; j++) {
                    int n = wn*32 + j*8 + 2*lc;
                    float v0 = acc[i][j][half*2 + 0] + bias[n]   + hsrow[n];
                    float v1 = acc[i][j][half*2 + 1] + bias[n+1] + hsrow[n+1];
                    acc[i][j][half*2 + 0] = v0;
                    acc[i][j][half*2 + 1] = v1;
                    s  += v0 + v1;
                    sq += v0*v0 + v1*v1;
                }
                s  += __shfl_xor_sync(0xffffffffu, s, 1);
                s  += __shfl_xor_sync(0xffffffffu, s, 2);
                sq += __shfl_xor_sync(0xffffffffu, sq, 1);
                sq += __shfl_xor_sync(0xffffffffu, sq, 2);
                if (lc == 0) { red_s[rl*4 + wn] = s; red_q[rl*4 + wn] = sq; }
            }
        }
        __syncthreads();
        #pragma unroll
        for (int i = 0; i < 4; i++) {
            #pragma unroll
            for (int half = 0; half < 2; half++) {
                int rl = wm*64 + i*16 + lr + half*8;
                float s  = red_s[rl*4+0] + red_s[rl*4+1] + red_s[rl*4+2] + red_s[rl*4+3];
                float sq = red_q[rl*4+0] + red_q[rl*4+1] + red_q[rl*4+2] + red_q[rl*4+3];
                float mu = s * (1.f/128.f);
                float var = sq * (1.f/128.f) - mu*mu;
                float rstd = rsqrtf(var + 1e-5f);
                size_t base = (size_t)(m0 + rl) * 128;
                #pragma unroll
                for (int j = 0; j < 4; j++) {
                    int n = wn*32 + j*8 + 2*lc;
                    float v0 = acc[i][j][half*2 + 0];
                    float v1 = acc[i][j][half*2 + 1];
                    *(float2*)&Cout[base + n] = make_float2(v0, v1);
                    float l0 = (v0 - mu)*rstd*gamma[n]   + beta[n];
                    float l1 = (v1 - mu)*rstd*gamma[n+1] + beta[n+1];
                    *(float2*)&ln_out[base + n] = make_float2(l0, l1);
                }
            }
        }
    } else {
        #pragma unroll
        for (int i = 0; i < 4; i++) {
            #pragma unroll
            for (int half = 0; half < 2; half++) {
                int m = m0 + wm*64 + i*16 + lr + half*8;
                size_t dstrow = (mode == 3) ? (size_t)perm_m(m) * 128 : (size_t)m * N;
                const float* addrow = (mode == 3) ? add + (size_t)m * 128 : nullptr;
                #pragma unroll
                for (int j = 0; j < 4; j++) {
                    int n = wn*32 + j*8 + 2*lc;
                    int ng = n0 + n;
                    float v0 = acc[i][j][half*2 + 0] + bias[ng];
                    float v1 = acc[i][j][half*2 + 1] + bias[ng+1];
                    if (mode == 0) { v0 *= sc; v1 *= sc; }
                    else if (mode == 2) {
                        v0 = 0.5f*v0*(1.0f + erff(v0*0.70710678118654752f));
                        v1 = 0.5f*v1*(1.0f + erff(v1*0.70710678118654752f));
                    } else {
                        v0 += addrow[n];
                        v1 += addrow[n+1];
                    }
                    *(float2*)&Cout[dstrow + ng] = make_float2(v0, v1);
                }
            }
        }
    }
}

// ---------------- windowed attention via tensor cores ----------------------
__global__ void __launch_bounds__(64) attn_kernel(
    const float* __restrict__ q, const float* __restrict__ k,
    const float* __restrict__ v, const float* __restrict__ rpb,
    float* __restrict__ out)
{
    __shared__ unsigned Qs[64*36];
    __shared__ unsigned Ks[64*36];
    __shared__ unsigned Vs[64*40];
    __shared__ unsigned Ps[64*68];
    __shared__ float    invs[64];

    const int win  = blockIdx.x >> 2;
    const int head = blockIdx.x & 3;
    const int tid  = threadIdx.x;
    const int lane = tid & 31;
    const int lr   = lane >> 2;
    const int lc   = lane & 3;
    const int w    = tid >> 5;
    const int wloc = win & 1023;
    const int wh = wloc >> 5, ww = wloc & 31;

    const size_t rowbase = ((size_t)win*64 + tid)*128 + head*32;

    #pragma unroll
    for (int d4 = 0; d4 < 8; d4++) {
        float4 qv = *(const float4*)(q + rowbase + d4*4);
        float4 kv = *(const float4*)(k + rowbase + d4*4);
        float4 vv = *(const float4*)(v + rowbase + d4*4);
        *(uint4*)&Qs[tid*36 + d4*4] = make_uint4(f2tf(qv.x), f2tf(qv.y), f2tf(qv.z), f2tf(qv.w));
        *(uint4*)&Ks[tid*36 + d4*4] = make_uint4(f2tf(kv.x), f2tf(kv.y), f2tf(kv.z), f2tf(kv.w));
        *(uint4*)&Vs[tid*40 + d4*4] = make_uint4(f2tf(vv.x), f2tf(vv.y), f2tf(vv.z), f2tf(vv.w));
    }
    __syncthreads();

    // S = Q @ K^T : warp w covers key-cols [w*32, w*32+32)
    {
        float s[4][4][4];
        #pragma unroll
        for (int i = 0; i < 4; i++)
            #pragma unroll
            for (int j = 0; j < 4; j++)
                #pragma unroll
                for (int c = 0; c < 4; c++) s[i][j][c] = 0.f;

        const int nb0 = w*32;
        #pragma unroll
        for (int kk = 0; kk < 32; kk += 8) {
            unsigned afr[4][4], bfr[4][2];
            #pragma unroll
            for (int i = 0; i < 4; i++) {
                int base = (i*16 + lr)*36 + kk + lc;
                afr[i][0] = Qs[base];
                afr[i][1] = Qs[base + 8*36];
                afr[i][2] = Qs[base + 4];
                afr[i][3] = Qs[base + 8*36 + 4];
            }
            #pragma unroll
            for (int j = 0; j < 4; j++) {
                int nn = nb0 + j*8 + lr;
                bfr[j][0] = Ks[nn*36 + kk + lc];
                bfr[j][1] = Ks[nn*36 + kk + lc + 4];
            }
            #pragma unroll
            for (int i = 0; i < 4; i++)
                #pragma unroll
                for (int j = 0; j < 4; j++)
                    mma_tf32(s[i][j], afr[i], bfr[j]);
        }
        #pragma unroll
        for (int i = 0; i < 4; i++)
            #pragma unroll
            for (int j = 0; j < 4; j++) {
                int row = i*16 + lr;
                int col = nb0 + j*8 + 2*lc;
                Ps[row*68 + col]          = __float_as_uint(s[i][j][0]);
                Ps[row*68 + col + 1]      = __float_as_uint(s[i][j][1]);
                Ps[(row+8)*68 + col]      = __float_as_uint(s[i][j][2]);
                Ps[(row+8)*68 + col + 1]  = __float_as_uint(s[i][j][3]);
            }
    }
    __syncthreads();

    // softmax: thread tid = query row
    {
        const int ti = tid >> 3, tj = tid & 7;
        const int myl = 3*region(wh*8 + ti) + region(ww*8 + tj);
        float mx = -1e30f;
        #pragma unroll 8
        for (int j = 0; j < 64; j++) {
            int ki = j >> 3, kj = j & 7;
            float sc = __uint_as_float(Ps[tid*68 + j]);
            sc += rpb[((ti - ki + 7)*15 + (tj - kj + 7))*4 + head];
            int jl = 3*region(wh*8 + ki) + region(ww*8 + kj);
            if (jl != myl) sc -= 100.f;
            Ps[tid*68 + j] = __float_as_uint(sc);
            mx = fmaxf(mx, sc);
        }
        float sum = 0.f;
        #pragma unroll 8
        for (int j = 0; j < 64; j++) {
            float e = __expf(__uint_as_float(Ps[tid*68 + j]) - mx);
            sum += e;
            Ps[tid*68 + j] = f2tf(e);
        }
        invs[tid] = 1.f / sum;
    }
    __syncthreads();

    // O = P @ V : warp w covers query rows [w*32, w*32+32)
    {
        float o[2][4][4];
        #pragma unroll
        for (int i = 0; i < 2; i++)
            #pragma unroll
            for (int j = 0; j < 4; j++)
                #pragma unroll
                for (int c = 0; c < 4; c++) o[i][j][c] = 0.f;

        const int mb = w*32;
        #pragma unroll
        for (int kk = 0; kk < 64; kk += 8) {
            unsigned afr[2][4], bfr[4][2];
            #pragma unroll
            for (int i = 0; i < 2; i++) {
                int base = (mb + i*16 + lr)*68 + kk + lc;
                afr[i][0] = Ps[base];
                afr[i][1] = Ps[base + 8*68];
                afr[i][2] = Ps[base + 4];
                afr[i][3] = Ps[base + 8*68 + 4];
            }
            #pragma unroll
            for (int j = 0; j < 4; j++) {
                int nn = j*8 + lr;
                bfr[j][0] = Vs[(kk + lc)*40 + nn];
                bfr[j][1] = Vs[(kk + lc + 4)*40 + nn];
            }
            #pragma unroll
            for (int i = 0; i < 2; i++)
                #pragma unroll
                for (int j = 0; j < 4; j++)
                    mma_tf32(o[i][j], afr[i], bfr[j]);
        }
        #pragma unroll
        for (int i = 0; i < 2; i++) {
            #pragma unroll
            for (int half = 0; half < 2; half++) {
                int row = mb + i*16 + lr + half*8;
                float inv = invs[row];
                size_t ob = ((size_t)win*64 + row)*128 + head*32;
                #pragma unroll
                for (int j = 0; j < 4; j++) {
                    int col = j*8 + 2*lc;
                    float v0 = o[i][j][half*2 + 0] * inv;
                    float v1 = o[i][j][half*2 + 1] * inv;
                    *(float2*)&out[ob + col] = make_float2(v0, v1);
                }
            }
        }
    }
}

// ---------------------------------------------------------------------------
extern "C" void kernel_launch(void* const* d_in, const int* in_sizes, int n_in,
                              void* d_out, int out_size)
{
    const float* hs   = (const float*)d_in[0];
    const float* l1s  = (const float*)d_in[1];
    const float* l1b  = (const float*)d_in[2];
    const float* qw   = (const float*)d_in[3];
    const float* qb   = (const float*)d_in[4];
    const float* kw   = (const float*)d_in[5];
    const float* kb   = (const float*)d_in[6];
    const float* vw   = (const float*)d_in[7];
    const float* vb   = (const float*)d_in[8];
    const float* pw   = (const float*)d_in[9];
    const float* pb   = (const float*)d_in[10];
    const float* rpb  = (const float*)d_in[11];
    const float* l2s  = (const float*)d_in[12];
    const float* l2b  = (const float*)d_in[13];
    const float* f1w  = (const float*)d_in[14];
    const float* f1b  = (const float*)d_in[15];
    const float* f2w  = (const float*)d_in[16];
    const float* f2b  = (const float*)d_in[17];
    float* outp = (float*)d_out;

    float *xw, *qx, *kx, *vx, *ao, *xr, *l2, *hbuf;
    cudaGetSymbolAddress((void**)&xw,   g_xw);
    cudaGetSymbolAddress((void**)&qx,   g_q);
    cudaGetSymbolAddress((void**)&kx,   g_k);
    cudaGetSymbolAddress((void**)&vx,   g_v);
    cudaGetSymbolAddress((void**)&ao,   g_ao);
    cudaGetSymbolAddress((void**)&xr,   g_xr);
    cudaGetSymbolAddress((void**)&l2,   g_l2);
    cudaGetSymbolAddress((void**)&hbuf, g_h);

    cudaFuncSetAttribute(gemm_tc, cudaFuncAttributeMaxDynamicSharedMemorySize, GEMM_SMEM);

    const float qscale = 0.17677669529663687f;  // 1/sqrt(32)

    // 1. LN1 + shift + window partition
    ln_kernel<<<MTOK/8, 256>>>(hs, l1s, l1b, xw, 1);
    // 2. fused QKV projections
    gemm_tc<<<dim3(3, MTOK/BM), 256, GEMM_SMEM>>>(xw, qw, qb, qx, kw, kb, kx, vw, vb, vx,
                                       128, 128, qscale, 0, nullptr, nullptr, nullptr, nullptr);
    // 3. windowed attention
    attn_kernel<<<4096*4, 64>>>(qx, kx, vx, rpb, ao);
    // 4. proj + shortcut(hs@perm) -> xr (window order), fused LN2 -> l2
    gemm_tc<<<dim3(1, MTOK/BM), 256, GEMM_SMEM>>>(ao, pw, pb, xr, nullptr, nullptr, nullptr, nullptr, nullptr, nullptr,
                                       128, 128, 1.0f, 1, hs, l2, l2s, l2b);
    // 5. fc1 + GELU (window order)
    gemm_tc<<<dim3(4, MTOK/BM), 256, GEMM_SMEM>>>(l2, f1w, f1b, hbuf, nullptr, nullptr, nullptr, nullptr, nullptr, nullptr,
                                       512, 128, 1.0f, 2, nullptr, nullptr, nullptr, nullptr);
    // 6. fc2 + residual(xr) -> out[perm(m)] (window reverse + unshift)
    gemm_tc<<<dim3(1, MTOK/BM), 256, GEMM_SMEM>>>(hbuf, f2w, f2b, outp, nullptr, nullptr, nullptr, nullptr, nullptr, nullptr,
                                       128, 512, 1.0f, 3, xr, nullptr, nullptr, nullptr);
}

// round 5
// speedup vs baseline: 3.5154x; 1.3748x over previous
#include <cuda_runtime.h>
#include <cuda_bf16.h>
#include <math.h>

#define MTOK 262144   // B*H*W = 4*256*256
#define CDIM 128
#define HID  512

// ---------------- scratch (device globals: allocation-free) ----------------
__device__ __nv_bfloat16 g_xw[(size_t)MTOK*CDIM];  // LN1 + shift + window partition
__device__ __nv_bfloat16 g_q [(size_t)MTOK*CDIM];
__device__ __nv_bfloat16 g_k [(size_t)MTOK*CDIM];
__device__ __nv_bfloat16 g_v [(size_t)MTOK*CDIM];
__device__ __nv_bfloat16 g_ao[(size_t)MTOK*CDIM];  // attention output (window order)
__device__ float         g_xr[(size_t)MTOK*CDIM];  // x = shortcut + proj (fp32 trunk!)
__device__ __nv_bfloat16 g_l2[(size_t)MTOK*CDIM];  // LN2(x)
__device__ __nv_bfloat16 g_h [(size_t)MTOK*HID];   // gelu(fc1)
__device__ __nv_bfloat16 g_wt[196608];             // transposed bf16 weights [N][K]

__device__ __forceinline__ int region(int a) { return a < 248 ? 0 : (a < 252 ? 1 : 2); }

__device__ __forceinline__ unsigned f2tf(float f) {
    unsigned u; asm("cvt.rna.tf32.f32 %0, %1;" : "=r"(u) : "f"(f)); return u;
}
__device__ __forceinline__ void mma_bf16(float c[4], const unsigned a[4], const unsigned b[2]) {
    asm volatile("mma.sync.aligned.m16n8k16.row.col.f32.bf16.bf16.f32 "
        "{%0,%1,%2,%3}, {%4,%5,%6,%7}, {%8,%9}, {%0,%1,%2,%3};\n"
        : "+f"(c[0]), "+f"(c[1]), "+f"(c[2]), "+f"(c[3])
        : "r"(a[0]), "r"(a[1]), "r"(a[2]), "r"(a[3]), "r"(b[0]), "r"(b[1]));
}
__device__ __forceinline__ void mma_tf32(float c[4], const unsigned a[4], const unsigned b[2]) {
    asm volatile("mma.sync.aligned.m16n8k8.row.col.f32.tf32.tf32.f32 "
        "{%0,%1,%2,%3}, {%4,%5,%6,%7}, {%8,%9}, {%0,%1,%2,%3};\n"
        : "+f"(c[0]), "+f"(c[1]), "+f"(c[2]), "+f"(c[3])
        : "r"(a[0]), "r"(a[1]), "r"(a[2]), "r"(a[3]), "r"(b[0]), "r"(b[1]));
}
__device__ __forceinline__ void cp16(unsigned dst, const void* src) {
    asm volatile("cp.async.cg.shared.global [%0], [%1], 16;\n" :: "r"(dst), "l"(src));
}
#define CP_COMMIT asm volatile("cp.async.commit_group;\n" ::: "memory")
#define CP_WAIT1  asm volatile("cp.async.wait_group 1;\n" ::: "memory")
#define CP_WAIT0  asm volatile("cp.async.wait_group 0;\n" ::: "memory")

// window-order index m -> original token index (window reverse + roll(+4,+4))
__device__ __forceinline__ int perm_m(int m) {
    int b = m >> 16, w = (m >> 6) & 1023, t = m & 63;
    int wh = w >> 5, ww = w & 31, ti = t >> 3, tj = t & 7;
    int r = (wh*8 + ti + 4) & 255;
    int c = (ww*8 + tj + 4) & 255;
    return (b << 16) | (r << 8) | c;
}

// ---------------- weight prep: W[K][N] fp32 -> Wt[N][K] bf16 ---------------
__global__ void prep_w(const float* __restrict__ w, __nv_bfloat16* __restrict__ wt,
                       int K, int N, int total)
{
    int idx = blockIdx.x * 256 + threadIdx.x;
    if (idx < total) {
        int n = idx / K, k = idx - n*K;
        wt[idx] = __float2bfloat16(w[(size_t)k * N + n]);
    }
}

// ---------------- LayerNorm (fused with shift+window gather), bf16 out -----
__global__ void ln_kernel(const float* __restrict__ in, const float* __restrict__ gamma,
                          const float* __restrict__ beta, __nv_bfloat16* __restrict__ out,
                          int gather)
{
    int token = blockIdx.x * 8 + (threadIdx.x >> 5);
    int lane  = threadIdx.x & 31;
    int src = gather ? perm_m(token) : token;
    float4 xv = ((const float4*)in)[(size_t)src*32 + lane];
    float s  = xv.x + xv.y + xv.z + xv.w;
    float sq = xv.x*xv.x + xv.y*xv.y + xv.z*xv.z + xv.w*xv.w;
    #pragma unroll
    for (int o = 16; o; o >>= 1) {
        s  += __shfl_xor_sync(0xffffffffu, s,  o);
        sq += __shfl_xor_sync(0xffffffffu, sq, o);
    }
    float mean = s * (1.f/128.f);
    float var  = sq * (1.f/128.f) - mean*mean;
    float rstd = rsqrtf(var + 1e-5f);
    float4 g  = ((const float4*)gamma)[lane];
    float4 bt = ((const float4*)beta)[lane];
    __nv_bfloat162 o0 = __floats2bfloat162_rn((xv.x - mean)*rstd*g.x + bt.x,
                                              (xv.y - mean)*rstd*g.y + bt.y);
    __nv_bfloat162 o1 = __floats2bfloat162_rn((xv.z - mean)*rstd*g.z + bt.z,
                                              (xv.w - mean)*rstd*g.w + bt.w);
    uint2 pk; pk.x = *(unsigned*)&o0; pk.y = *(unsigned*)&o1;
    ((uint2*)out)[(size_t)token*32 + lane] = pk;
}

// ---------------- bf16 tensor-core GEMM: C[M,N] = A[M,K] @ Wt[N][K]^T ------
// BM=128, BN=128, BK=32. 256 threads = 8 warps (2m x 4n), warptile 64x32.
// A: [M][K] bf16 row-major. Wt: [N][K] bf16 (k contiguous). 3-stage cp.async.
// modes: 0 fused QKV | 1 proj+shortcut+LN2 | 2 gelu | 3 fc2+residual+perm
#define BM 128
#define BN 128
#define BK 32
#define ASTR 20   // uints/row (16 used + 4 pad); (20*lr+lc)%32 bijective
#define BSTR 20
#define NST 3
#define SA_W (BM*ASTR)
#define SB_W (BN*BSTR)
#define GEMM_SMEM ((NST*(SA_W + SB_W))*4 + BM*4*4*2)

__global__ void __launch_bounds__(256, 2) gemm_tc(
    const __nv_bfloat16* __restrict__ A,
    const __nv_bfloat16* __restrict__ W0, const float* __restrict__ B0, void* __restrict__ C0v,
    const __nv_bfloat16* __restrict__ W1, const float* __restrict__ B1, void* __restrict__ C1v,
    const __nv_bfloat16* __restrict__ W2, const float* __restrict__ B2, void* __restrict__ C2v,
    int N, int K, float scale, int mode,
    const float* __restrict__ add, __nv_bfloat16* __restrict__ ln_out,
    const float* __restrict__ gamma, const float* __restrict__ beta)
{
    extern __shared__ unsigned smem[];
    unsigned* AsB = smem;
    unsigned* BsB = smem + NST*SA_W;
    float* red_s = (float*)(smem + NST*(SA_W + SB_W));
    float* red_q = red_s + BM*4;

    const int tid  = threadIdx.x;
    const int lane = tid & 31;
    const int lr   = lane >> 2;
    const int lc   = lane & 3;
    const int w    = tid >> 5;
    const int wm   = w >> 2;
    const int wn   = w & 3;
    const int m0   = blockIdx.y * BM;

    const __nv_bfloat16* Bw; const float* bias; void* Cout; float sc; int n0;
    if (mode == 0) {
        int s = blockIdx.x;
        Bw   = s == 0 ? W0 : (s == 1 ? W1 : W2);
        bias = s == 0 ? B0 : (s == 1 ? B1 : B2);
        Cout = s == 0 ? C0v : (s == 1 ? C1v : C2v);
        sc   = s == 0 ? scale : 1.0f;
        n0   = 0;
    } else {
        Bw = W0; bias = B0; Cout = C0v; sc = 1.0f;
        n0 = blockIdx.x * BN;
    }

    // global src coords: 16B chunk = 8 bf16; 4 chunks/row of BK=32
    const int grow = tid >> 2;            // 0..63 (+64)
    const int gc8  = (tid & 3) << 3;      // bf16 offset within k-slice

    const __nv_bfloat16* Ap0 = A  + (size_t)(m0 + grow) * K + gc8;
    const __nv_bfloat16* Ap1 = Ap0 + (size_t)64 * K;
    const __nv_bfloat16* Bp0 = Bw + (size_t)(n0 + grow) * K + gc8;
    const __nv_bfloat16* Bp1 = Bp0 + (size_t)64 * K;

    const unsigned a_base = (unsigned)__cvta_generic_to_shared(AsB);
    const unsigned b_base = (unsigned)__cvta_generic_to_shared(BsB);
    const unsigned a_s0 = a_base + (grow*ASTR + (tid & 3)*4)*4;
    const unsigned a_s1 = a_base + ((grow+64)*ASTR + (tid & 3)*4)*4;
    const unsigned b_s0 = b_base + (grow*BSTR + (tid & 3)*4)*4;
    const unsigned b_s1 = b_base + ((grow+64)*BSTR + (tid & 3)*4)*4;
    const unsigned SAB = SA_W*4, SBB = SB_W*4;

    const int stages = K >> 5;

    #define ISSUE(t, buf) { \
        int kt_ = (t) << 5; \
        cp16(a_s0 + (buf)*SAB, Ap0 + kt_); \
        cp16(a_s1 + (buf)*SAB, Ap1 + kt_); \
        cp16(b_s0 + (buf)*SBB, Bp0 + kt_); \
        cp16(b_s1 + (buf)*SBB, Bp1 + kt_); \
        CP_COMMIT; }

    ISSUE(0, 0);
    ISSUE(1, 1);
    CP_WAIT1;
    __syncthreads();

    float acc[4][4][4];
    #pragma unroll
    for (int i = 0; i < 4; i++)
        #pragma unroll
        for (int j = 0; j < 4; j++)
            #pragma unroll
            for (int c = 0; c < 4; c++) acc[i][j][c] = 0.f;

    const int a_off = (wm*64 + lr)*ASTR + lc;
    const int b_off = (wn*32 + lr)*BSTR + lc;

    for (int t = 0; t < stages; t++) {
        const unsigned* as = AsB + (t % NST)*SA_W;
        const unsigned* bs = BsB + (t % NST)*SB_W;
        #pragma unroll
        for (int kk2 = 0; kk2 < 16; kk2 += 8) {     // uint offset: k=16 per step
            unsigned afr[4][4];
            #pragma unroll
            for (int i = 0; i < 4; i++) {
                int base = a_off + i*16*ASTR + kk2;
                afr[i][0] = as[base];
                afr[i][1] = as[base + 8*ASTR];
                afr[i][2] = as[base + 4];
                afr[i][3] = as[base + 8*ASTR + 4];
            }
            #pragma unroll
            for (int j = 0; j < 4; j++) {
                unsigned bfr[2];
                int bb = b_off + j*8*BSTR + kk2;
                bfr[0] = bs[bb];
                bfr[1] = bs[bb + 4];
                #pragma unroll
                for (int i = 0; i < 4; i++)
                    mma_bf16(acc[i][j], afr[i], bfr);
            }
        }
        if (t + 2 < stages) {
            ISSUE(t + 2, (t + 2) % NST);
            CP_WAIT1;
            __syncthreads();
        } else if (t + 1 < stages) {
            CP_WAIT0;
            __syncthreads();
        }
    }
    #undef ISSUE

    // ---------------- epilogue ----------------
    if (mode == 1) {
        float* Cx = (float*)Cout;
        #pragma unroll
        for (int i = 0; i < 4; i++) {
            #pragma unroll
            for (int half = 0; half < 2; half++) {
                int rl = wm*64 + i*16 + lr + half*8;
                int m  = m0 + rl;
                const float* hsrow = add + (size_t)perm_m(m) * 128;
                float s = 0.f, sq = 0.f;
                #pragma unroll
                for (int j = 0; j < 4; j++) {
                    int n = wn*32 + j*8 + 2*lc;
                    float v0 = acc[i][j][half*2 + 0] + bias[n]   + hsrow[n];
                    float v1 = acc[i][j][half*2 + 1] + bias[n+1] + hsrow[n+1];
                    acc[i][j][half*2 + 0] = v0;
                    acc[i][j][half*2 + 1] = v1;
                    s  += v0 + v1;
                    sq += v0*v0 + v1*v1;
                }
                s  += __shfl_xor_sync(0xffffffffu, s, 1);
                s  += __shfl_xor_sync(0xffffffffu, s, 2);
                sq += __shfl_xor_sync(0xffffffffu, sq, 1);
                sq += __shfl_xor_sync(0xffffffffu, sq, 2);
                if (lc == 0) { red_s[rl*4 + wn] = s; red_q[rl*4 + wn] = sq; }
            }
        }
        __syncthreads();
        #pragma unroll
        for (int i = 0; i < 4; i++) {
            #pragma unroll
            for (int half = 0; half < 2; half++) {
                int rl = wm*64 + i*16 + lr + half*8;
                float s  = red_s[rl*4+0] + red_s[rl*4+1] + red_s[rl*4+2] + red_s[rl*4+3];
                float sq = red_q[rl*4+0] + red_q[rl*4+1] + red_q[rl*4+2] + red_q[rl*4+3];
                float mu = s * (1.f/128.f);
                float var = sq * (1.f/128.f) - mu*mu;
                float rstd = rsqrtf(var + 1e-5f);
                size_t base = (size_t)(m0 + rl) * 128;
                #pragma unroll
                for (int j = 0; j < 4; j++) {
                    int n = wn*32 + j*8 + 2*lc;
                    float v0 = acc[i][j][half*2 + 0];
                    float v1 = acc[i][j][half*2 + 1];
                    *(float2*)&Cx[base + n] = make_float2(v0, v1);
                    float l0 = (v0 - mu)*rstd*gamma[n]   + beta[n];
                    float l1 = (v1 - mu)*rstd*gamma[n+1] + beta[n+1];
                    __nv_bfloat162 lb = __floats2bfloat162_rn(l0, l1);
                    *(__nv_bfloat162*)&ln_out[base + n] = lb;
                }
            }
        }
    } else if (mode == 3) {
        float* Cx = (float*)Cout;
        #pragma unroll
        for (int i = 0; i < 4; i++) {
            #pragma unroll
            for (int half = 0; half < 2; half++) {
                int m = m0 + wm*64 + i*16 + lr + half*8;
                size_t dstrow = (size_t)perm_m(m) * 128;
                const float* addrow = add + (size_t)m * 128;
                #pragma unroll
                for (int j = 0; j < 4; j++) {
                    int n = wn*32 + j*8 + 2*lc;
                    float v0 = acc[i][j][half*2 + 0] + bias[n] + addrow[n];
                    float v1 = acc[i][j][half*2 + 1] + bias[n+1] + addrow[n+1];
                    *(float2*)&Cx[dstrow + n] = make_float2(v0, v1);
                }
            }
        }
    } else {
        __nv_bfloat16* Cb = (__nv_bfloat16*)Cout;
        #pragma unroll
        for (int i = 0; i < 4; i++) {
            #pragma unroll
            for (int half = 0; half < 2; half++) {
                int m = m0 + wm*64 + i*16 + lr + half*8;
                size_t dstrow = (size_t)m * N;
                #pragma unroll
                for (int j = 0; j < 4; j++) {
                    int n = wn*32 + j*8 + 2*lc;
                    int ng = n0 + n;
                    float v0 = acc[i][j][half*2 + 0] + bias[ng];
                    float v1 = acc[i][j][half*2 + 1] + bias[ng+1];
                    if (mode == 0) { v0 *= sc; v1 *= sc; }
                    else {
                        v0 = 0.5f*v0*(1.0f + erff(v0*0.70710678118654752f));
                        v1 = 0.5f*v1*(1.0f + erff(v1*0.70710678118654752f));
                    }
                    __nv_bfloat162 vb = __floats2bfloat162_rn(v0, v1);
                    *(__nv_bfloat162*)&Cb[dstrow + ng] = vb;
                }
            }
        }
    }
}

// ---------------- windowed attention: bf16 QK^T mma + tf32 PV mma ----------
__global__ void __launch_bounds__(64) attn_kernel(
    const __nv_bfloat16* __restrict__ q, const __nv_bfloat16* __restrict__ k,
    const __nv_bfloat16* __restrict__ v, const float* __restrict__ rpb,
    __nv_bfloat16* __restrict__ out)
{
    __shared__ unsigned Qs[64*20];   // bf16 pairs along d
    __shared__ unsigned Ks[64*20];
    __shared__ unsigned Vs[64*40];   // tf32 (fp32 bits from bf16)
    __shared__ unsigned Ps[64*68];
    __shared__ float    invs[64];

    const int win  = blockIdx.x >> 2;
    const int head = blockIdx.x & 3;
    const int tid  = threadIdx.x;
    const int lane = tid & 31;
    const int lr   = lane >> 2;
    const int lc   = lane & 3;
    const int w    = tid >> 5;
    const int wloc = win & 1023;
    const int wh = wloc >> 5, ww = wloc & 31;

    const size_t rowbase = ((size_t)win*64 + tid)*128 + head*32;

    // load q/k rows as bf16 pair uints; v unpacked to tf32-compatible fp32 bits
    {
        const uint4* qp = (const uint4*)(q + rowbase);
        const uint4* kp = (const uint4*)(k + rowbase);
        const uint4* vp = (const uint4*)(v + rowbase);
        #pragma unroll
        for (int u4 = 0; u4 < 4; u4++) {
            uint4 qq = qp[u4];
            uint4 kk = kp[u4];
            uint4 vv = vp[u4];
            *(uint4*)&Qs[tid*20 + u4*4] = qq;
            *(uint4*)&Ks[tid*20 + u4*4] = kk;
            unsigned* vd = &Vs[tid*40 + u4*8];
            vd[0] = vv.x << 16; vd[1] = vv.x & 0xffff0000u;
            vd[2] = vv.y << 16; vd[3] = vv.y & 0xffff0000u;
            vd[4] = vv.z << 16; vd[5] = vv.z & 0xffff0000u;
            vd[6] = vv.w << 16; vd[7] = vv.w & 0xffff0000u;
        }
    }
    __syncthreads();

    // S = Q @ K^T (bf16 mma): warp w covers key-cols [w*32, w*32+32)
    {
        float s[4][4][4];
        #pragma unroll
        for (int i = 0; i < 4; i++)
            #pragma unroll
            for (int j = 0; j < 4; j++)
                #pragma unroll
                for (int c = 0; c < 4; c++) s[i][j][c] = 0.f;

        const int nb0 = w*32;
        #pragma unroll
        for (int kk2 = 0; kk2 < 16; kk2 += 8) {
            unsigned afr[4][4], bfr[4][2];
            #pragma unroll
            for (int i = 0; i < 4; i++) {
                int base = (i*16 + lr)*20 + kk2 + lc;
                afr[i][0] = Qs[base];
                afr[i][1] = Qs[base + 8*20];
                afr[i][2] = Qs[base + 4];
                afr[i][3] = Qs[base + 8*20 + 4];
            }
            #pragma unroll
            for (int j = 0; j < 4; j++) {
                int nn = nb0 + j*8 + lr;
                bfr[j][0] = Ks[nn*20 + kk2 + lc];
                bfr[j][1] = Ks[nn*20 + kk2 + lc + 4];
            }
            #pragma unroll
            for (int i = 0; i < 4; i++)
                #pragma unroll
                for (int j = 0; j < 4; j++)
                    mma_bf16(s[i][j], afr[i], bfr[j]);
        }
        #pragma unroll
        for (int i = 0; i < 4; i++)
            #pragma unroll
            for (int j = 0; j < 4; j++) {
                int row = i*16 + lr;
                int col = nb0 + j*8 + 2*lc;
                Ps[row*68 + col]          = __float_as_uint(s[i][j][0]);
                Ps[row*68 + col + 1]      = __float_as_uint(s[i][j][1]);
                Ps[(row+8)*68 + col]      = __float_as_uint(s[i][j][2]);
                Ps[(row+8)*68 + col + 1]  = __float_as_uint(s[i][j][3]);
            }
    }
    __syncthreads();

    // softmax: thread tid = query row
    {
        const int ti = tid >> 3, tj = tid & 7;
        const int myl = 3*region(wh*8 + ti) + region(ww*8 + tj);
        float mx = -1e30f;
        #pragma unroll 8
        for (int j = 0; j < 64; j++) {
            int ki = j >> 3, kj = j & 7;
            float sc = __uint_as_float(Ps[tid*68 + j]);
            sc += rpb[((ti - ki + 7)*15 + (tj - kj + 7))*4 + head];
            int jl = 3*region(wh*8 + ki) + region(ww*8 + kj);
            if (jl != myl) sc -= 100.f;
            Ps[tid*68 + j] = __float_as_uint(sc);
            mx = fmaxf(mx, sc);
        }
        float sum = 0.f;
        #pragma unroll 8
        for (int j = 0; j < 64; j++) {
            float e = __expf(__uint_as_float(Ps[tid*68 + j]) - mx);
            sum += e;
            Ps[tid*68 + j] = f2tf(e);
        }
        invs[tid] = 1.f / sum;
    }
    __syncthreads();

    // O = P @ V (tf32 mma): warp w covers query rows [w*32, w*32+32)
    {
        float o[2][4][4];
        #pragma unroll
        for (int i = 0; i < 2; i++)
            #pragma unroll
            for (int j = 0; j < 4; j++)
                #pragma unroll
                for (int c = 0; c < 4; c++) o[i][j][c] = 0.f;

        const int mb = w*32;
        #pragma unroll
        for (int kk = 0; kk < 64; kk += 8) {
            unsigned afr[2][4], bfr[4][2];
            #pragma unroll
            for (int i = 0; i < 2; i++) {
                int base = (mb + i*16 + lr)*68 + kk + lc;
                afr[i][0] = Ps[base];
                afr[i][1] = Ps[base + 8*68];
                afr[i][2] = Ps[base + 4];
                afr[i][3] = Ps[base + 8*68 + 4];
            }
            #pragma unroll
            for (int j = 0; j < 4; j++) {
                int nn = j*8 + lr;
                bfr[j][0] = Vs[(kk + lc)*40 + nn];
                bfr[j][1] = Vs[(kk + lc + 4)*40 + nn];
            }
            #pragma unroll
            for (int i = 0; i < 2; i++)
                #pragma unroll
                for (int j = 0; j < 4; j++)
                    mma_tf32(o[i][j], afr[i], bfr[j]);
        }
        #pragma unroll
        for (int i = 0; i < 2; i++) {
            #pragma unroll
            for (int half = 0; half < 2; half++) {
                int row = mb + i*16 + lr + half*8;
                float inv = invs[row];
                size_t ob = ((size_t)win*64 + row)*128 + head*32;
                #pragma unroll
                for (int j = 0; j < 4; j++) {
                    int col = j*8 + 2*lc;
                    __nv_bfloat162 vb = __floats2bfloat162_rn(
                        o[i][j][half*2 + 0] * inv, o[i][j][half*2 + 1] * inv);
                    *(__nv_bfloat162*)&out[ob + col] = vb;
                }
            }
        }
    }
}

// ---------------------------------------------------------------------------
extern "C" void kernel_launch(void* const* d_in, const int* in_sizes, int n_in,
                              void* d_out, int out_size)
{
    const float* hs   = (const float*)d_in[0];
    const float* l1s  = (const float*)d_in[1];
    const float* l1b  = (const float*)d_in[2];
    const float* qw   = (const float*)d_in[3];
    const float* qb   = (const float*)d_in[4];
    const float* kw   = (const float*)d_in[5];
    const float* kb   = (const float*)d_in[6];
    const float* vw   = (const float*)d_in[7];
    const float* vb   = (const float*)d_in[8];
    const float* pw   = (const float*)d_in[9];
    const float* pb   = (const float*)d_in[10];
    const float* rpb  = (const float*)d_in[11];
    const float* l2s  = (const float*)d_in[12];
    const float* l2b  = (const float*)d_in[13];
    const float* f1w  = (const float*)d_in[14];
    const float* f1b  = (const float*)d_in[15];
    const float* f2w  = (const float*)d_in[16];
    const float* f2b  = (const float*)d_in[17];
    float* outp = (float*)d_out;

    __nv_bfloat16 *xw, *qx, *kx, *vx, *ao, *l2, *hbuf, *wt;
    float *xr;
    cudaGetSymbolAddress((void**)&xw,   g_xw);
    cudaGetSymbolAddress((void**)&qx,   g_q);
    cudaGetSymbolAddress((void**)&kx,   g_k);
    cudaGetSymbolAddress((void**)&vx,   g_v);
    cudaGetSymbolAddress((void**)&ao,   g_ao);
    cudaGetSymbolAddress((void**)&xr,   g_xr);
    cudaGetSymbolAddress((void**)&l2,   g_l2);
    cudaGetSymbolAddress((void**)&hbuf, g_h);
    cudaGetSymbolAddress((void**)&wt,   g_wt);

    __nv_bfloat16* qt  = wt;
    __nv_bfloat16* kt  = wt + 16384;
    __nv_bfloat16* vt  = wt + 32768;
    __nv_bfloat16* pt  = wt + 49152;
    __nv_bfloat16* f1t = wt + 65536;   // [512][128]
    __nv_bfloat16* f2t = wt + 131072;  // [128][512]

    cudaFuncSetAttribute(gemm_tc, cudaFuncAttributeMaxDynamicSharedMemorySize, GEMM_SMEM);

    const float qscale = 0.17677669529663687f;  // 1/sqrt(32)

    // 0. weight prep (tiny)
    prep_w<<<64, 256>>>(qw, qt, 128, 128, 16384);
    prep_w<<<64, 256>>>(kw, kt, 128, 128, 16384);
    prep_w<<<64, 256>>>(vw, vt, 128, 128, 16384);
    prep_w<<<64, 256>>>(pw, pt, 128, 128, 16384);
    prep_w<<<256, 256>>>(f1w, f1t, 128, 512, 65536);
    prep_w<<<256, 256>>>(f2w, f2t, 512, 128, 65536);

    // 1. LN1 + shift + window partition (bf16 out)
    ln_kernel<<<MTOK/8, 256>>>(hs, l1s, l1b, xw, 1);
    // 2. fused QKV projections
    gemm_tc<<<dim3(3, MTOK/BM), 256, GEMM_SMEM>>>(xw, qt, qb, qx, kt, kb, kx, vt, vb, vx,
                                       128, 128, qscale, 0, nullptr, nullptr, nullptr, nullptr);
    // 3. windowed attention
    attn_kernel<<<4096*4, 64>>>(qx, kx, vx, rpb, ao);
    // 4. proj + shortcut(hs@perm) -> xr fp32 (window order), fused LN2 -> l2 bf16
    gemm_tc<<<dim3(1, MTOK/BM), 256, GEMM_SMEM>>>(ao, pt, pb, xr, nullptr, nullptr, nullptr,
                                       nullptr, nullptr, nullptr,
                                       128, 128, 1.0f, 1, hs, l2, l2s, l2b);
    // 5. fc1 + GELU (bf16 out)
    gemm_tc<<<dim3(4, MTOK/BM), 256, GEMM_SMEM>>>(l2, f1t, f1b, hbuf, nullptr, nullptr, nullptr,
                                       nullptr, nullptr, nullptr,
                                       512, 128, 1.0f, 2, nullptr, nullptr, nullptr, nullptr);
    // 6. fc2 + residual(xr) -> out[perm(m)] fp32
    gemm_tc<<<dim3(1, MTOK/BM), 256, GEMM_SMEM>>>(hbuf, f2t, f2b, outp, nullptr, nullptr, nullptr,
                                       nullptr, nullptr, nullptr,
                                       128, 512, 1.0f, 3, xr, nullptr, nullptr, nullptr);
}

// round 6
// speedup vs baseline: 3.5595x; 1.0125x over previous
#include <cuda_runtime.h>
#include <cuda_bf16.h>
#include <math.h>

#define MTOK 262144   // B*H*W = 4*256*256
#define CDIM 128
#define HID  512

// ---------------- scratch (device globals: allocation-free) ----------------
__device__ __nv_bfloat16 g_xw[(size_t)MTOK*CDIM];  // LN1 + shift + window partition
__device__ __nv_bfloat16 g_q [(size_t)MTOK*CDIM];
__device__ __nv_bfloat16 g_k [(size_t)MTOK*CDIM];
__device__ __nv_bfloat16 g_v [(size_t)MTOK*CDIM];
__device__ __nv_bfloat16 g_ao[(size_t)MTOK*CDIM];  // attention output (window order)
__device__ __nv_bfloat16 g_dl[(size_t)MTOK*CDIM];  // delta = proj_out + bias (bf16, window order)
__device__ __nv_bfloat16 g_l2[(size_t)MTOK*CDIM];  // LN2(hs[perm] + delta)
__device__ __nv_bfloat16 g_h [(size_t)MTOK*HID];   // gelu(fc1)
__device__ __nv_bfloat16 g_wt[196608];             // transposed bf16 weights [N][K]

__device__ __forceinline__ int region(int a) { return a < 248 ? 0 : (a < 252 ? 1 : 2); }

__device__ __forceinline__ unsigned f2tf(float f) {
    unsigned u; asm("cvt.rna.tf32.f32 %0, %1;" : "=r"(u) : "f"(f)); return u;
}
__device__ __forceinline__ void mma_bf16(float c[4], const unsigned a[4], const unsigned b[2]) {
    asm volatile("mma.sync.aligned.m16n8k16.row.col.f32.bf16.bf16.f32 "
        "{%0,%1,%2,%3}, {%4,%5,%6,%7}, {%8,%9}, {%0,%1,%2,%3};\n"
        : "+f"(c[0]), "+f"(c[1]), "+f"(c[2]), "+f"(c[3])
        : "r"(a[0]), "r"(a[1]), "r"(a[2]), "r"(a[3]), "r"(b[0]), "r"(b[1]));
}
__device__ __forceinline__ void mma_tf32(float c[4], const unsigned a[4], const unsigned b[2]) {
    asm volatile("mma.sync.aligned.m16n8k8.row.col.f32.tf32.tf32.f32 "
        "{%0,%1,%2,%3}, {%4,%5,%6,%7}, {%8,%9}, {%0,%1,%2,%3};\n"
        : "+f"(c[0]), "+f"(c[1]), "+f"(c[2]), "+f"(c[3])
        : "r"(a[0]), "r"(a[1]), "r"(a[2]), "r"(a[3]), "r"(b[0]), "r"(b[1]));
}
__device__ __forceinline__ void cp16(unsigned dst, const void* src) {
    asm volatile("cp.async.cg.shared.global [%0], [%1], 16;\n" :: "r"(dst), "l"(src));
}
#define CP_COMMIT asm volatile("cp.async.commit_group;\n" ::: "memory")
#define CP_WAIT1  asm volatile("cp.async.wait_group 1;\n" ::: "memory")
#define CP_WAIT0  asm volatile("cp.async.wait_group 0;\n" ::: "memory")

// window-order index m -> original token index (window reverse + roll(+4,+4))
__device__ __forceinline__ int perm_m(int m) {
    int b = m >> 16, w = (m >> 6) & 1023, t = m & 63;
    int wh = w >> 5, ww = w & 31, ti = t >> 3, tj = t & 7;
    int r = (wh*8 + ti + 4) & 255;
    int c = (ww*8 + tj + 4) & 255;
    return (b << 16) | (r << 8) | c;
}

// ---------------- fused weight prep: all six matrices in one launch --------
__global__ void prep_all(const float* __restrict__ qw, const float* __restrict__ kw,
                         const float* __restrict__ vw, const float* __restrict__ pw,
                         const float* __restrict__ f1w, const float* __restrict__ f2w,
                         __nv_bfloat16* __restrict__ wt)
{
    int idx = blockIdx.x * 256 + threadIdx.x;     // 0..196607
    float v;
    if (idx < 65536) {
        int seg = idx >> 14;
        int rel = idx & 16383;
        int n = rel >> 7, k = rel & 127;
        const float* src = seg == 0 ? qw : (seg == 1 ? kw : (seg == 2 ? vw : pw));
        v = src[k*128 + n];
    } else if (idx < 131072) {
        int rel = idx - 65536;            // f1t [512][128] <- f1w [128][512]
        int n = rel >> 7, k = rel & 127;
        v = f1w[k*512 + n];
    } else {
        int rel = idx - 131072;           // f2t [128][512] <- f2w [512][128]
        int n = rel >> 9, k = rel & 511;
        v = f2w[k*128 + n];
    }
    wt[idx] = __float2bfloat16(v);
}

// ---------------- LayerNorm (fused with shift+window gather), bf16 out -----
__global__ void ln_kernel(const float* __restrict__ in, const float* __restrict__ gamma,
                          const float* __restrict__ beta, __nv_bfloat16* __restrict__ out,
                          int gather)
{
    int token = blockIdx.x * 8 + (threadIdx.x >> 5);
    int lane  = threadIdx.x & 31;
    int src = gather ? perm_m(token) : token;
    float4 xv = ((const float4*)in)[(size_t)src*32 + lane];
    float s  = xv.x + xv.y + xv.z + xv.w;
    float sq = xv.x*xv.x + xv.y*xv.y + xv.z*xv.z + xv.w*xv.w;
    #pragma unroll
    for (int o = 16; o; o >>= 1) {
        s  += __shfl_xor_sync(0xffffffffu, s,  o);
        sq += __shfl_xor_sync(0xffffffffu, sq, o);
    }
    float mean = s * (1.f/128.f);
    float var  = sq * (1.f/128.f) - mean*mean;
    float rstd = rsqrtf(var + 1e-5f);
    float4 g  = ((const float4*)gamma)[lane];
    float4 bt = ((const float4*)beta)[lane];
    __nv_bfloat162 o0 = __floats2bfloat162_rn((xv.x - mean)*rstd*g.x + bt.x,
                                              (xv.y - mean)*rstd*g.y + bt.y);
    __nv_bfloat162 o1 = __floats2bfloat162_rn((xv.z - mean)*rstd*g.z + bt.z,
                                              (xv.w - mean)*rstd*g.w + bt.w);
    uint2 pk; pk.x = *(unsigned*)&o0; pk.y = *(unsigned*)&o1;
    ((uint2*)out)[(size_t)token*32 + lane] = pk;
}

// ---------------- bf16 tensor-core GEMM: C[M,N] = A[M,K] @ Wt[N][K]^T ------
// BM=128, BN=128, BK=32. 256 threads = 8 warps (2m x 4n), warptile 64x32.
// modes: 0 fused QKV | 1 proj: delta bf16 + LN2(hs+delta) | 2 gelu | 3 fc2: hs+delta+acc -> perm
#define BM 128
#define BN 128
#define BK 32
#define ASTR 20
#define BSTR 20
#define NST 3
#define SA_W (BM*ASTR)
#define SB_W (BN*BSTR)
#define GEMM_SMEM ((NST*(SA_W + SB_W))*4 + BM*4*4*2)

__global__ void __launch_bounds__(256, 2) gemm_tc(
    const __nv_bfloat16* __restrict__ A,
    const __nv_bfloat16* __restrict__ W0, const float* __restrict__ B0, void* __restrict__ C0v,
    const __nv_bfloat16* __restrict__ W1, const float* __restrict__ B1, void* __restrict__ C1v,
    const __nv_bfloat16* __restrict__ W2, const float* __restrict__ B2, void* __restrict__ C2v,
    int N, int K, float scale, int mode,
    const float* __restrict__ add, __nv_bfloat16* __restrict__ aux_bf,
    const float* __restrict__ gamma, const float* __restrict__ beta)
{
    extern __shared__ unsigned smem[];
    unsigned* AsB = smem;
    unsigned* BsB = smem + NST*SA_W;
    float* red_s = (float*)(smem + NST*(SA_W + SB_W));
    float* red_q = red_s + BM*4;

    const int tid  = threadIdx.x;
    const int lane = tid & 31;
    const int lr   = lane >> 2;
    const int lc   = lane & 3;
    const int w    = tid >> 5;
    const int wm   = w >> 2;
    const int wn   = w & 3;
    const int m0   = blockIdx.y * BM;

    const __nv_bfloat16* Bw; const float* bias; void* Cout; float sc; int n0;
    if (mode == 0) {
        int s = blockIdx.x;
        Bw   = s == 0 ? W0 : (s == 1 ? W1 : W2);
        bias = s == 0 ? B0 : (s == 1 ? B1 : B2);
        Cout = s == 0 ? C0v : (s == 1 ? C1v : C2v);
        sc   = s == 0 ? scale : 1.0f;
        n0   = 0;
    } else {
        Bw = W0; bias = B0; Cout = C0v; sc = 1.0f;
        n0 = blockIdx.x * BN;
    }

    const int grow = tid >> 2;
    const int gc8  = (tid & 3) << 3;

    const __nv_bfloat16* Ap0 = A  + (size_t)(m0 + grow) * K + gc8;
    const __nv_bfloat16* Ap1 = Ap0 + (size_t)64 * K;
    const __nv_bfloat16* Bp0 = Bw + (size_t)(n0 + grow) * K + gc8;
    const __nv_bfloat16* Bp1 = Bp0 + (size_t)64 * K;

    const unsigned a_base = (unsigned)__cvta_generic_to_shared(AsB);
    const unsigned b_base = (unsigned)__cvta_generic_to_shared(BsB);
    const unsigned a_s0 = a_base + (grow*ASTR + (tid & 3)*4)*4;
    const unsigned a_s1 = a_base + ((grow+64)*ASTR + (tid & 3)*4)*4;
    const unsigned b_s0 = b_base + (grow*BSTR + (tid & 3)*4)*4;
    const unsigned b_s1 = b_base + ((grow+64)*BSTR + (tid & 3)*4)*4;
    const unsigned SAB = SA_W*4, SBB = SB_W*4;

    const int stages = K >> 5;

    #define ISSUE(t, buf) { \
        int kt_ = (t) << 5; \
        cp16(a_s0 + (buf)*SAB, Ap0 + kt_); \
        cp16(a_s1 + (buf)*SAB, Ap1 + kt_); \
        cp16(b_s0 + (buf)*SBB, Bp0 + kt_); \
        cp16(b_s1 + (buf)*SBB, Bp1 + kt_); \
        CP_COMMIT; }

    ISSUE(0, 0);
    ISSUE(1, 1);
    CP_WAIT1;
    __syncthreads();

    float acc[4][4][4];
    #pragma unroll
    for (int i = 0; i < 4; i++)
        #pragma unroll
        for (int j = 0; j < 4; j++)
            #pragma unroll
            for (int c = 0; c < 4; c++) acc[i][j][c] = 0.f;

    const int a_off = (wm*64 + lr)*ASTR + lc;
    const int b_off = (wn*32 + lr)*BSTR + lc;

    for (int t = 0; t < stages; t++) {
        const unsigned* as = AsB + (t % NST)*SA_W;
        const unsigned* bs = BsB + (t % NST)*SB_W;
        #pragma unroll
        for (int kk2 = 0; kk2 < 16; kk2 += 8) {
            unsigned afr[4][4];
            #pragma unroll
            for (int i = 0; i < 4; i++) {
                int base = a_off + i*16*ASTR + kk2;
                afr[i][0] = as[base];
                afr[i][1] = as[base + 8*ASTR];
                afr[i][2] = as[base + 4];
                afr[i][3] = as[base + 8*ASTR + 4];
            }
            #pragma unroll
            for (int j = 0; j < 4; j++) {
                unsigned bfr[2];
                int bb = b_off + j*8*BSTR + kk2;
                bfr[0] = bs[bb];
                bfr[1] = bs[bb + 4];
                #pragma unroll
                for (int i = 0; i < 4; i++)
                    mma_bf16(acc[i][j], afr[i], bfr);
            }
        }
        if (t + 2 < stages) {
            ISSUE(t + 2, (t + 2) % NST);
            CP_WAIT1;
            __syncthreads();
        } else if (t + 1 < stages) {
            CP_WAIT0;
            __syncthreads();
        }
    }
    #undef ISSUE

    // ---------------- epilogue ----------------
    if (mode == 1) {
        // delta = acc + bias (bf16 out); x = delta + hs[perm]; LN2(x) -> aux_bf
        __nv_bfloat16* Cd = (__nv_bfloat16*)Cout;
        #pragma unroll
        for (int i = 0; i < 4; i++) {
            #pragma unroll
            for (int half = 0; half < 2; half++) {
                int rl = wm*64 + i*16 + lr + half*8;
                int m  = m0 + rl;
                const float* hsrow = add + (size_t)perm_m(m) * 128;
                size_t drow = (size_t)m * 128;
                float s = 0.f, sq = 0.f;
                #pragma unroll
                for (int j = 0; j < 4; j++) {
                    int n = wn*32 + j*8 + 2*lc;
                    float d0 = acc[i][j][half*2 + 0] + bias[n];
                    float d1 = acc[i][j][half*2 + 1] + bias[n+1];
                    __nv_bfloat162 db = __floats2bfloat162_rn(d0, d1);
                    *(__nv_bfloat162*)&Cd[drow + n] = db;
                    float v0 = d0 + hsrow[n];
                    float v1 = d1 + hsrow[n+1];
                    acc[i][j][half*2 + 0] = v0;
                    acc[i][j][half*2 + 1] = v1;
                    s  += v0 + v1;
                    sq += v0*v0 + v1*v1;
                }
                s  += __shfl_xor_sync(0xffffffffu, s, 1);
                s  += __shfl_xor_sync(0xffffffffu, s, 2);
                sq += __shfl_xor_sync(0xffffffffu, sq, 1);
                sq += __shfl_xor_sync(0xffffffffu, sq, 2);
                if (lc == 0) { red_s[rl*4 + wn] = s; red_q[rl*4 + wn] = sq; }
            }
        }
        __syncthreads();
        #pragma unroll
        for (int i = 0; i < 4; i++) {
            #pragma unroll
            for (int half = 0; half < 2; half++) {
                int rl = wm*64 + i*16 + lr + half*8;
                float s  = red_s[rl*4+0] + red_s[rl*4+1] + red_s[rl*4+2] + red_s[rl*4+3];
                float sq = red_q[rl*4+0] + red_q[rl*4+1] + red_q[rl*4+2] + red_q[rl*4+3];
                float mu = s * (1.f/128.f);
                float var = sq * (1.f/128.f) - mu*mu;
                float rstd = rsqrtf(var + 1e-5f);
                size_t base = (size_t)(m0 + rl) * 128;
                #pragma unroll
                for (int j = 0; j < 4; j++) {
                    int n = wn*32 + j*8 + 2*lc;
                    float l0 = (acc[i][j][half*2 + 0] - mu)*rstd*gamma[n]   + beta[n];
                    float l1 = (acc[i][j][half*2 + 1] - mu)*rstd*gamma[n+1] + beta[n+1];
                    __nv_bfloat162 lb = __floats2bfloat162_rn(l0, l1);
                    *(__nv_bfloat162*)&aux_bf[base + n] = lb;
                }
            }
        }
    } else if (mode == 3) {
        // out[perm(m)] = acc + bias + hs[perm(m)] + delta[m]
        float* Cx = (float*)Cout;
        const __nv_bfloat16* dl = aux_bf;
        #pragma unroll
        for (int i = 0; i < 4; i++) {
            #pragma unroll
            for (int half = 0; half < 2; half++) {
                int m = m0 + wm*64 + i*16 + lr + half*8;
                size_t dstrow = (size_t)perm_m(m) * 128;
                const float* hsrow = add + dstrow;
                const __nv_bfloat16* drow = dl + (size_t)m * 128;
                #pragma unroll
                for (int j = 0; j < 4; j++) {
                    int n = wn*32 + j*8 + 2*lc;
                    __nv_bfloat162 db = *(const __nv_bfloat162*)&drow[n];
                    float v0 = acc[i][j][half*2 + 0] + bias[n]   + hsrow[n]   + __bfloat162float(db.x);
                    float v1 = acc[i][j][half*2 + 1] + bias[n+1] + hsrow[n+1] + __bfloat162float(db.y);
                    *(float2*)&Cx[dstrow + n] = make_float2(v0, v1);
                }
            }
        }
    } else {
        __nv_bfloat16* Cb = (__nv_bfloat16*)Cout;
        #pragma unroll
        for (int i = 0; i < 4; i++) {
            #pragma unroll
            for (int half = 0; half < 2; half++) {
                int m = m0 + wm*64 + i*16 + lr + half*8;
                size_t dstrow = (size_t)m * N;
                #pragma unroll
                for (int j = 0; j < 4; j++) {
                    int n = wn*32 + j*8 + 2*lc;
                    int ng = n0 + n;
                    float v0 = acc[i][j][half*2 + 0] + bias[ng];
                    float v1 = acc[i][j][half*2 + 1] + bias[ng+1];
                    if (mode == 0) { v0 *= sc; v1 *= sc; }
                    else {
                        v0 = 0.5f*v0*(1.0f + erff(v0*0.70710678118654752f));
                        v1 = 0.5f*v1*(1.0f + erff(v1*0.70710678118654752f));
                    }
                    __nv_bfloat162 vb = __floats2bfloat162_rn(v0, v1);
                    *(__nv_bfloat162*)&Cb[dstrow + ng] = vb;
                }
            }
        }
    }
}

// ---------------- windowed attention: bf16 QK^T mma + tf32 PV mma ----------
__global__ void __launch_bounds__(64) attn_kernel(
    const __nv_bfloat16* __restrict__ q, const __nv_bfloat16* __restrict__ k,
    const __nv_bfloat16* __restrict__ v, const float* __restrict__ rpb,
    __nv_bfloat16* __restrict__ out)
{
    __shared__ unsigned Qs[64*20];   // bf16 pairs along d
    __shared__ unsigned Ks[64*20];
    __shared__ unsigned Vs[64*40];   // tf32-compatible fp32 bits
    __shared__ unsigned Ps[64*68];
    __shared__ float    invs[64];

    const int win  = blockIdx.x >> 2;
    const int head = blockIdx.x & 3;
    const int tid  = threadIdx.x;
    const int lane = tid & 31;
    const int lr   = lane >> 2;
    const int lc   = lane & 3;
    const int w    = tid >> 5;
    const int wloc = win & 1023;
    const int wh = wloc >> 5, ww = wloc & 31;

    // coalesced loads: thread -> (token, 16B chunk); warp covers 8 contiguous 64B slices
    {
        const __nv_bfloat16* qb_ = q + (size_t)win*64*128 + head*32;
        const __nv_bfloat16* kb_ = k + (size_t)win*64*128 + head*32;
        const __nv_bfloat16* vb_ = v + (size_t)win*64*128 + head*32;
        #pragma unroll
        for (int i = 0; i < 4; i++) {
            int idx = tid + 64*i;          // 0..255
            int tok = idx >> 2, ch = idx & 3;
            size_t off = (size_t)tok*128 + ch*8;
            uint4 qq = *(const uint4*)(qb_ + off);
            uint4 kk = *(const uint4*)(kb_ + off);
            uint4 vv = *(const uint4*)(vb_ + off);
            *(uint4*)&Qs[tok*20 + ch*4] = qq;
            *(uint4*)&Ks[tok*20 + ch*4] = kk;
            unsigned* vd = &Vs[tok*40 + ch*8];
            vd[0] = vv.x << 16; vd[1] = vv.x & 0xffff0000u;
            vd[2] = vv.y << 16; vd[3] = vv.y & 0xffff0000u;
            vd[4] = vv.z << 16; vd[5] = vv.z & 0xffff0000u;
            vd[6] = vv.w << 16; vd[7] = vv.w & 0xffff0000u;
        }
    }
    __syncthreads();

    // S = Q @ K^T (bf16 mma): warp w covers key-cols [w*32, w*32+32)
    {
        float s[4][4][4];
        #pragma unroll
        for (int i = 0; i < 4; i++)
            #pragma unroll
            for (int j = 0; j < 4; j++)
                #pragma unroll
                for (int c = 0; c < 4; c++) s[i][j][c] = 0.f;

        const int nb0 = w*32;
        #pragma unroll
        for (int kk2 = 0; kk2 < 16; kk2 += 8) {
            unsigned afr[4][4], bfr[4][2];
            #pragma unroll
            for (int i = 0; i < 4; i++) {
                int base = (i*16 + lr)*20 + kk2 + lc;
                afr[i][0] = Qs[base];
                afr[i][1] = Qs[base + 8*20];
                afr[i][2] = Qs[base + 4];
                afr[i][3] = Qs[base + 8*20 + 4];
            }
            #pragma unroll
            for (int j = 0; j < 4; j++) {
                int nn = nb0 + j*8 + lr;
                bfr[j][0] = Ks[nn*20 + kk2 + lc];
                bfr[j][1] = Ks[nn*20 + kk2 + lc + 4];
            }
            #pragma unroll
            for (int i = 0; i < 4; i++)
                #pragma unroll
                for (int j = 0; j < 4; j++)
                    mma_bf16(s[i][j], afr[i], bfr[j]);
        }
        #pragma unroll
        for (int i = 0; i < 4; i++)
            #pragma unroll
            for (int j = 0; j < 4; j++) {
                int row = i*16 + lr;
                int col = nb0 + j*8 + 2*lc;
                Ps[row*68 + col]          = __float_as_uint(s[i][j][0]);
                Ps[row*68 + col + 1]      = __float_as_uint(s[i][j][1]);
                Ps[(row+8)*68 + col]      = __float_as_uint(s[i][j][2]);
                Ps[(row+8)*68 + col + 1]  = __float_as_uint(s[i][j][3]);
            }
    }
    __syncthreads();

    // softmax: thread tid = query row
    {
        const int ti = tid >> 3, tj = tid & 7;
        const int myl = 3*region(wh*8 + ti) + region(ww*8 + tj);
        float mx = -1e30f;
        #pragma unroll 8
        for (int j = 0; j < 64; j++) {
            int ki = j >> 3, kj = j & 7;
            float sc = __uint_as_float(Ps[tid*68 + j]);
            sc += rpb[((ti - ki + 7)*15 + (tj - kj + 7))*4 + head];
            int jl = 3*region(wh*8 + ki) + region(ww*8 + kj);
            if (jl != myl) sc -= 100.f;
            Ps[tid*68 + j] = __float_as_uint(sc);
            mx = fmaxf(mx, sc);
        }
        float sum = 0.f;
        #pragma unroll 8
        for (int j = 0; j < 64; j++) {
            float e = __expf(__uint_as_float(Ps[tid*68 + j]) - mx);
            sum += e;
            Ps[tid*68 + j] = f2tf(e);
        }
        invs[tid] = 1.f / sum;
    }
    __syncthreads();

    // O = P @ V (tf32 mma): warp w covers query rows [w*32, w*32+32)
    {
        float o[2][4][4];
        #pragma unroll
        for (int i = 0; i < 2; i++)
            #pragma unroll
            for (int j = 0; j < 4; j++)
                #pragma unroll
                for (int c = 0; c < 4; c++) o[i][j][c] = 0.f;

        const int mb = w*32;
        #pragma unroll
        for (int kk = 0; kk < 64; kk += 8) {
            unsigned afr[2][4], bfr[4][2];
            #pragma unroll
            for (int i = 0; i < 2; i++) {
                int base = (mb + i*16 + lr)*68 + kk + lc;
                afr[i][0] = Ps[base];
                afr[i][1] = Ps[base + 8*68];
                afr[i][2] = Ps[base + 4];
                afr[i][3] = Ps[base + 8*68 + 4];
            }
            #pragma unroll
            for (int j = 0; j < 4; j++) {
                int nn = j*8 + lr;
                bfr[j][0] = Vs[(kk + lc)*40 + nn];
                bfr[j][1] = Vs[(kk + lc + 4)*40 + nn];
            }
            #pragma unroll
            for (int i = 0; i < 2; i++)
                #pragma unroll
                for (int j = 0; j < 4; j++)
                    mma_tf32(o[i][j], afr[i], bfr[j]);
        }
        #pragma unroll
        for (int i = 0; i < 2; i++) {
            #pragma unroll
            for (int half = 0; half < 2; half++) {
                int row = mb + i*16 + lr + half*8;
                float inv = invs[row];
                size_t ob = ((size_t)win*64 + row)*128 + head*32;
                #pragma unroll
                for (int j = 0; j < 4; j++) {
                    int col = j*8 + 2*lc;
                    __nv_bfloat162 vb = __floats2bfloat162_rn(
                        o[i][j][half*2 + 0] * inv, o[i][j][half*2 + 1] * inv);
                    *(__nv_bfloat162*)&out[ob + col] = vb;
                }
            }
        }
    }
}

// ---------------------------------------------------------------------------
extern "C" void kernel_launch(void* const* d_in, const int* in_sizes, int n_in,
                              void* d_out, int out_size)
{
    const float* hs   = (const float*)d_in[0];
    const float* l1s  = (const float*)d_in[1];
    const float* l1b  = (const float*)d_in[2];
    const float* qw   = (const float*)d_in[3];
    const float* qb   = (const float*)d_in[4];
    const float* kw   = (const float*)d_in[5];
    const float* kb   = (const float*)d_in[6];
    const float* vw   = (const float*)d_in[7];
    const float* vb   = (const float*)d_in[8];
    const float* pw   = (const float*)d_in[9];
    const float* pb   = (const float*)d_in[10];
    const float* rpb  = (const float*)d_in[11];
    const float* l2s  = (const float*)d_in[12];
    const float* l2b  = (const float*)d_in[13];
    const float* f1w  = (const float*)d_in[14];
    const float* f1b  = (const float*)d_in[15];
    const float* f2w  = (const float*)d_in[16];
    const float* f2b  = (const float*)d_in[17];
    float* outp = (float*)d_out;

    __nv_bfloat16 *xw, *qx, *kx, *vx, *ao, *dl, *l2, *hbuf, *wt;
    cudaGetSymbolAddress((void**)&xw,   g_xw);
    cudaGetSymbolAddress((void**)&qx,   g_q);
    cudaGetSymbolAddress((void**)&kx,   g_k);
    cudaGetSymbolAddress((void**)&vx,   g_v);
    cudaGetSymbolAddress((void**)&ao,   g_ao);
    cudaGetSymbolAddress((void**)&dl,   g_dl);
    cudaGetSymbolAddress((void**)&l2,   g_l2);
    cudaGetSymbolAddress((void**)&hbuf, g_h);
    cudaGetSymbolAddress((void**)&wt,   g_wt);

    __nv_bfloat16* qt  = wt;
    __nv_bfloat16* kt  = wt + 16384;
    __nv_bfloat16* vt  = wt + 32768;
    __nv_bfloat16* pt  = wt + 49152;
    __nv_bfloat16* f1t = wt + 65536;   // [512][128]
    __nv_bfloat16* f2t = wt + 131072;  // [128][512]

    cudaFuncSetAttribute(gemm_tc, cudaFuncAttributeMaxDynamicSharedMemorySize, GEMM_SMEM);

    const float qscale = 0.17677669529663687f;  // 1/sqrt(32)

    // 0. fused weight prep (single launch)
    prep_all<<<768, 256>>>(qw, kw, vw, pw, f1w, f2w, wt);
    // 1. LN1 + shift + window partition (bf16 out)
    ln_kernel<<<MTOK/8, 256>>>(hs, l1s, l1b, xw, 1);
    // 2. fused QKV projections
    gemm_tc<<<dim3(3, MTOK/BM), 256, GEMM_SMEM>>>(xw, qt, qb, qx, kt, kb, kx, vt, vb, vx,
                                       128, 128, qscale, 0, nullptr, nullptr, nullptr, nullptr);
    // 3. windowed attention
    attn_kernel<<<4096*4, 64>>>(qx, kx, vx, rpb, ao);
    // 4. proj -> delta bf16 (window order); LN2(hs[perm]+delta) -> l2
    gemm_tc<<<dim3(1, MTOK/BM), 256, GEMM_SMEM>>>(ao, pt, pb, dl, nullptr, nullptr, nullptr,
                                       nullptr, nullptr, nullptr,
                                       128, 128, 1.0f, 1, hs, l2, l2s, l2b);
    // 5. fc1 + GELU (bf16 out)
    gemm_tc<<<dim3(4, MTOK/BM), 256, GEMM_SMEM>>>(l2, f1t, f1b, hbuf, nullptr, nullptr, nullptr,
                                       nullptr, nullptr, nullptr,
                                       512, 128, 1.0f, 2, nullptr, nullptr, nullptr, nullptr);
    // 6. fc2: out[perm] = acc + bias + hs[perm] + delta  (fp32 out)
    gemm_tc<<<dim3(1, MTOK/BM), 256, GEMM_SMEM>>>(hbuf, f2t, f2b, outp, nullptr, nullptr, nullptr,
                                       nullptr, nullptr, nullptr,
                                       128, 512, 1.0f, 3, hs, dl, nullptr, nullptr);
}

// round 7
// speedup vs baseline: 3.8747x; 1.0886x over previous
#include <cuda_runtime.h>
#include <cuda_bf16.h>
#include <math.h>

#define MTOK 262144   // B*H*W = 4*256*256
#define CDIM 128
#define HID  512

// ---------------- scratch (device globals: allocation-free) ----------------
__device__ __nv_bfloat16 g_xw[(size_t)MTOK*CDIM];  // LN1 + shift + window partition
__device__ __nv_bfloat16 g_q [(size_t)MTOK*CDIM];
__device__ __nv_bfloat16 g_k [(size_t)MTOK*CDIM];
__device__ __nv_bfloat16 g_v [(size_t)MTOK*CDIM];
__device__ __nv_bfloat16 g_ao[(size_t)MTOK*CDIM];  // attention output (window order)
__device__ __nv_bfloat16 g_dl[(size_t)MTOK*CDIM];  // delta = proj_out + bias (bf16, window order)
__device__ __nv_bfloat16 g_l2[(size_t)MTOK*CDIM];  // LN2(hs[perm] + delta)
__device__ __nv_bfloat16 g_h [(size_t)MTOK*HID];   // gelu(fc1)
__device__ __nv_bfloat16 g_wt[196608];             // transposed bf16 weights [N][K]

__device__ __forceinline__ int region(int a) { return a < 248 ? 0 : (a < 252 ? 1 : 2); }

__device__ __forceinline__ void mma_bf16(float c[4], const unsigned a[4], const unsigned b[2]) {
    asm volatile("mma.sync.aligned.m16n8k16.row.col.f32.bf16.bf16.f32 "
        "{%0,%1,%2,%3}, {%4,%5,%6,%7}, {%8,%9}, {%0,%1,%2,%3};\n"
        : "+f"(c[0]), "+f"(c[1]), "+f"(c[2]), "+f"(c[3])
        : "r"(a[0]), "r"(a[1]), "r"(a[2]), "r"(a[3]), "r"(b[0]), "r"(b[1]));
}
__device__ __forceinline__ void cp16(unsigned dst, const void* src) {
    asm volatile("cp.async.cg.shared.global [%0], [%1], 16;\n" :: "r"(dst), "l"(src));
}
#define CP_COMMIT asm volatile("cp.async.commit_group;\n" ::: "memory")
#define CP_WAIT1  asm volatile("cp.async.wait_group 1;\n" ::: "memory")
#define CP_WAIT0  asm volatile("cp.async.wait_group 0;\n" ::: "memory")

// window-order index m -> original token index (window reverse + roll(+4,+4))
__device__ __forceinline__ int perm_m(int m) {
    int b = m >> 16, w = (m >> 6) & 1023, t = m & 63;
    int wh = w >> 5, ww = w & 31, ti = t >> 3, tj = t & 7;
    int r = (wh*8 + ti + 4) & 255;
    int c = (ww*8 + tj + 4) & 255;
    return (b << 16) | (r << 8) | c;
}
__device__ __forceinline__ unsigned packbf(float a, float b) {
    __nv_bfloat162 t = __floats2bfloat162_rn(a, b);
    return *(unsigned*)&t;
}

// ---------------- fused weight prep: all six matrices in one launch --------
__global__ void prep_all(const float* __restrict__ qw, const float* __restrict__ kw,
                         const float* __restrict__ vw, const float* __restrict__ pw,
                         const float* __restrict__ f1w, const float* __restrict__ f2w,
                         __nv_bfloat16* __restrict__ wt)
{
    int idx = blockIdx.x * 256 + threadIdx.x;     // 0..196607
    float v;
    if (idx < 65536) {
        int seg = idx >> 14;
        int rel = idx & 16383;
        int n = rel >> 7, k = rel & 127;
        const float* src = seg == 0 ? qw : (seg == 1 ? kw : (seg == 2 ? vw : pw));
        v = src[k*128 + n];
    } else if (idx < 131072) {
        int rel = idx - 65536;            // f1t [512][128] <- f1w [128][512]
        int n = rel >> 7, k = rel & 127;
        v = f1w[k*512 + n];
    } else {
        int rel = idx - 131072;           // f2t [128][512] <- f2w [512][128]
        int n = rel >> 9, k = rel & 511;
        v = f2w[k*128 + n];
    }
    wt[idx] = __float2bfloat16(v);
}

// ---------------- LayerNorm (fused with shift+window gather), bf16 out -----
__global__ void ln_kernel(const float* __restrict__ in, const float* __restrict__ gamma,
                          const float* __restrict__ beta, __nv_bfloat16* __restrict__ out,
                          int gather)
{
    int token = blockIdx.x * 8 + (threadIdx.x >> 5);
    int lane  = threadIdx.x & 31;
    int src = gather ? perm_m(token) : token;
    float4 xv = ((const float4*)in)[(size_t)src*32 + lane];
    float s  = xv.x + xv.y + xv.z + xv.w;
    float sq = xv.x*xv.x + xv.y*xv.y + xv.z*xv.z + xv.w*xv.w;
    #pragma unroll
    for (int o = 16; o; o >>= 1) {
        s  += __shfl_xor_sync(0xffffffffu, s,  o);
        sq += __shfl_xor_sync(0xffffffffu, sq, o);
    }
    float mean = s * (1.f/128.f);
    float var  = sq * (1.f/128.f) - mean*mean;
    float rstd = rsqrtf(var + 1e-5f);
    float4 g  = ((const float4*)gamma)[lane];
    float4 bt = ((const float4*)beta)[lane];
    uint2 pk;
    pk.x = packbf((xv.x - mean)*rstd*g.x + bt.x, (xv.y - mean)*rstd*g.y + bt.y);
    pk.y = packbf((xv.z - mean)*rstd*g.z + bt.z, (xv.w - mean)*rstd*g.w + bt.w);
    ((uint2*)out)[(size_t)token*32 + lane] = pk;
}

// ---------------- bf16 tensor-core GEMM: C[M,N] = A[M,K] @ Wt[N][K]^T ------
#define BM 128
#define BN 128
#define BK 32
#define ASTR 20
#define BSTR 20
#define NST 3
#define SA_W (BM*ASTR)
#define SB_W (BN*BSTR)
#define GEMM_SMEM ((NST*(SA_W + SB_W))*4 + BM*4*4*2)

__global__ void __launch_bounds__(256, 2) gemm_tc(
    const __nv_bfloat16* __restrict__ A,
    const __nv_bfloat16* __restrict__ W0, const float* __restrict__ B0, void* __restrict__ C0v,
    const __nv_bfloat16* __restrict__ W1, const float* __restrict__ B1, void* __restrict__ C1v,
    const __nv_bfloat16* __restrict__ W2, const float* __restrict__ B2, void* __restrict__ C2v,
    int N, int K, float scale, int mode,
    const float* __restrict__ add, __nv_bfloat16* __restrict__ aux_bf,
    const float* __restrict__ gamma, const float* __restrict__ beta)
{
    extern __shared__ unsigned smem[];
    unsigned* AsB = smem;
    unsigned* BsB = smem + NST*SA_W;
    float* red_s = (float*)(smem + NST*(SA_W + SB_W));
    float* red_q = red_s + BM*4;

    const int tid  = threadIdx.x;
    const int lane = tid & 31;
    const int lr   = lane >> 2;
    const int lc   = lane & 3;
    const int w    = tid >> 5;
    const int wm   = w >> 2;
    const int wn   = w & 3;
    const int m0   = blockIdx.y * BM;

    const __nv_bfloat16* Bw; const float* bias; void* Cout; float sc; int n0;
    if (mode == 0) {
        int s = blockIdx.x;
        Bw   = s == 0 ? W0 : (s == 1 ? W1 : W2);
        bias = s == 0 ? B0 : (s == 1 ? B1 : B2);
        Cout = s == 0 ? C0v : (s == 1 ? C1v : C2v);
        sc   = s == 0 ? scale : 1.0f;
        n0   = 0;
    } else {
        Bw = W0; bias = B0; Cout = C0v; sc = 1.0f;
        n0 = blockIdx.x * BN;
    }

    const int grow = tid >> 2;
    const int gc8  = (tid & 3) << 3;

    const __nv_bfloat16* Ap0 = A  + (size_t)(m0 + grow) * K + gc8;
    const __nv_bfloat16* Ap1 = Ap0 + (size_t)64 * K;
    const __nv_bfloat16* Bp0 = Bw + (size_t)(n0 + grow) * K + gc8;
    const __nv_bfloat16* Bp1 = Bp0 + (size_t)64 * K;

    const unsigned a_base = (unsigned)__cvta_generic_to_shared(AsB);
    const unsigned b_base = (unsigned)__cvta_generic_to_shared(BsB);
    const unsigned a_s0 = a_base + (grow*ASTR + (tid & 3)*4)*4;
    const unsigned a_s1 = a_base + ((grow+64)*ASTR + (tid & 3)*4)*4;
    const unsigned b_s0 = b_base + (grow*BSTR + (tid & 3)*4)*4;
    const unsigned b_s1 = b_base + ((grow+64)*BSTR + (tid & 3)*4)*4;
    const unsigned SAB = SA_W*4, SBB = SB_W*4;

    const int stages = K >> 5;

    #define ISSUE(t, buf) { \
        int kt_ = (t) << 5; \
        cp16(a_s0 + (buf)*SAB, Ap0 + kt_); \
        cp16(a_s1 + (buf)*SAB, Ap1 + kt_); \
        cp16(b_s0 + (buf)*SBB, Bp0 + kt_); \
        cp16(b_s1 + (buf)*SBB, Bp1 + kt_); \
        CP_COMMIT; }

    ISSUE(0, 0);
    ISSUE(1, 1);
    CP_WAIT1;
    __syncthreads();

    float acc[4][4][4];
    #pragma unroll
    for (int i = 0; i < 4; i++)
        #pragma unroll
        for (int j = 0; j < 4; j++)
            #pragma unroll
            for (int c = 0; c < 4; c++) acc[i][j][c] = 0.f;

    const int a_off = (wm*64 + lr)*ASTR + lc;
    const int b_off = (wn*32 + lr)*BSTR + lc;

    for (int t = 0; t < stages; t++) {
        const unsigned* as = AsB + (t % NST)*SA_W;
        const unsigned* bs = BsB + (t % NST)*SB_W;
        #pragma unroll
        for (int kk2 = 0; kk2 < 16; kk2 += 8) {
            unsigned afr[4][4];
            #pragma unroll
            for (int i = 0; i < 4; i++) {
                int base = a_off + i*16*ASTR + kk2;
                afr[i][0] = as[base];
                afr[i][1] = as[base + 8*ASTR];
                afr[i][2] = as[base + 4];
                afr[i][3] = as[base + 8*ASTR + 4];
            }
            #pragma unroll
            for (int j = 0; j < 4; j++) {
                unsigned bfr[2];
                int bb = b_off + j*8*BSTR + kk2;
                bfr[0] = bs[bb];
                bfr[1] = bs[bb + 4];
                #pragma unroll
                for (int i = 0; i < 4; i++)
                    mma_bf16(acc[i][j], afr[i], bfr);
            }
        }
        if (t + 2 < stages) {
            ISSUE(t + 2, (t + 2) % NST);
            CP_WAIT1;
            __syncthreads();
        } else if (t + 1 < stages) {
            CP_WAIT0;
            __syncthreads();
        }
    }
    #undef ISSUE

    // ---------------- epilogue ----------------
    if (mode == 1) {
        __nv_bfloat16* Cd = (__nv_bfloat16*)Cout;
        #pragma unroll
        for (int i = 0; i < 4; i++) {
            #pragma unroll
            for (int half = 0; half < 2; half++) {
                int rl = wm*64 + i*16 + lr + half*8;
                int m  = m0 + rl;
                const float* hsrow = add + (size_t)perm_m(m) * 128;
                size_t drow = (size_t)m * 128;
                float s = 0.f, sq = 0.f;
                #pragma unroll
                for (int j = 0; j < 4; j++) {
                    int n = wn*32 + j*8 + 2*lc;
                    float d0 = acc[i][j][half*2 + 0] + bias[n];
                    float d1 = acc[i][j][half*2 + 1] + bias[n+1];
                    *(unsigned*)&Cd[drow + n] = packbf(d0, d1);
                    float v0 = d0 + hsrow[n];
                    float v1 = d1 + hsrow[n+1];
                    acc[i][j][half*2 + 0] = v0;
                    acc[i][j][half*2 + 1] = v1;
                    s  += v0 + v1;
                    sq += v0*v0 + v1*v1;
                }
                s  += __shfl_xor_sync(0xffffffffu, s, 1);
                s  += __shfl_xor_sync(0xffffffffu, s, 2);
                sq += __shfl_xor_sync(0xffffffffu, sq, 1);
                sq += __shfl_xor_sync(0xffffffffu, sq, 2);
                if (lc == 0) { red_s[rl*4 + wn] = s; red_q[rl*4 + wn] = sq; }
            }
        }
        __syncthreads();
        #pragma unroll
        for (int i = 0; i < 4; i++) {
            #pragma unroll
            for (int half = 0; half < 2; half++) {
                int rl = wm*64 + i*16 + lr + half*8;
                float s  = red_s[rl*4+0] + red_s[rl*4+1] + red_s[rl*4+2] + red_s[rl*4+3];
                float sq = red_q[rl*4+0] + red_q[rl*4+1] + red_q[rl*4+2] + red_q[rl*4+3];
                float mu = s * (1.f/128.f);
                float var = sq * (1.f/128.f) - mu*mu;
                float rstd = rsqrtf(var + 1e-5f);
                size_t base = (size_t)(m0 + rl) * 128;
                #pragma unroll
                for (int j = 0; j < 4; j++) {
                    int n = wn*32 + j*8 + 2*lc;
                    float l0 = (acc[i][j][half*2 + 0] - mu)*rstd*gamma[n]   + beta[n];
                    float l1 = (acc[i][j][half*2 + 1] - mu)*rstd*gamma[n+1] + beta[n+1];
                    *(unsigned*)&aux_bf[base + n] = packbf(l0, l1);
                }
            }
        }
    } else if (mode == 3) {
        float* Cx = (float*)Cout;
        const __nv_bfloat16* dl = aux_bf;
        #pragma unroll
        for (int i = 0; i < 4; i++) {
            #pragma unroll
            for (int half = 0; half < 2; half++) {
                int m = m0 + wm*64 + i*16 + lr + half*8;
                size_t dstrow = (size_t)perm_m(m) * 128;
                const float* hsrow = add + dstrow;
                const __nv_bfloat16* drow = dl + (size_t)m * 128;
                #pragma unroll
                for (int j = 0; j < 4; j++) {
                    int n = wn*32 + j*8 + 2*lc;
                    __nv_bfloat162 db = *(const __nv_bfloat162*)&drow[n];
                    float v0 = acc[i][j][half*2 + 0] + bias[n]   + hsrow[n]   + __bfloat162float(db.x);
                    float v1 = acc[i][j][half*2 + 1] + bias[n+1] + hsrow[n+1] + __bfloat162float(db.y);
                    *(float2*)&Cx[dstrow + n] = make_float2(v0, v1);
                }
            }
        }
    } else {
        __nv_bfloat16* Cb = (__nv_bfloat16*)Cout;
        #pragma unroll
        for (int i = 0; i < 4; i++) {
            #pragma unroll
            for (int half = 0; half < 2; half++) {
                int m = m0 + wm*64 + i*16 + lr + half*8;
                size_t dstrow = (size_t)m * N;
                #pragma unroll
                for (int j = 0; j < 4; j++) {
                    int n = wn*32 + j*8 + 2*lc;
                    int ng = n0 + n;
                    float v0 = acc[i][j][half*2 + 0] + bias[ng];
                    float v1 = acc[i][j][half*2 + 1] + bias[ng+1];
                    if (mode == 0) { v0 *= sc; v1 *= sc; }
                    else {
                        v0 = 0.5f*v0*(1.0f + erff(v0*0.70710678118654752f));
                        v1 = 0.5f*v1*(1.0f + erff(v1*0.70710678118654752f));
                    }
                    *(unsigned*)&Cb[dstrow + ng] = packbf(v0, v1);
                }
            }
        }
    }
}

// ---------------- windowed attention: all-bf16 mma, in-register softmax ----
// One block per (window, head), 64 threads = 2 warps.
// S mma: warp w owns all 64 rows x key-cols [32w,32w+32). Softmax on the
// accumulators (bias+mask in-register; cross-warp max/sum via 64x2 smem).
// P packed bf16 -> Ps; V stored transposed bf16 [n][k] -> PV bf16 mma with
// per-warp k-partials combined through one smem exchange.
__global__ void __launch_bounds__(64) attn_kernel(
    const __nv_bfloat16* __restrict__ q, const __nv_bfloat16* __restrict__ k,
    const __nv_bfloat16* __restrict__ v, const float* __restrict__ rpb,
    __nv_bfloat16* __restrict__ out)
{
    __shared__ unsigned Qs[64*20];     // bf16 pairs along d, stride 20 uints
    __shared__ unsigned Ks[64*20];
    __shared__ unsigned Vt[32*36];     // V^T bf16 pairs along k: [n][kpair], stride 36
    __shared__ unsigned Ps[64*36];     // P bf16 pairs along k; reused as float Osum[64*34]
    __shared__ float    rpb_s[225];
    __shared__ int      lab_s[64];
    __shared__ float    redm[128];     // [row][warp] partial max
    __shared__ float    redsum[128];   // [row][warp] partial sum

    const int win  = blockIdx.x >> 2;
    const int head = blockIdx.x & 3;
    const int tid  = threadIdx.x;
    const int lane = tid & 31;
    const int lr   = lane >> 2;
    const int lc   = lane & 3;
    const int w    = tid >> 5;
    const int wloc = win & 1023;
    const int wh = wloc >> 5, ww = wloc & 31;

    // stage rpb column for this head + region labels
    for (int idx = tid; idx < 225; idx += 64) rpb_s[idx] = rpb[idx*4 + head];
    lab_s[tid] = 3*region(wh*8 + (tid >> 3)) + region(ww*8 + (tid & 7));

    // coalesced loads: thread -> (token, 16B chunk)
    {
        const __nv_bfloat16* qb_ = q + (size_t)win*64*128 + head*32;
        const __nv_bfloat16* kb_ = k + (size_t)win*64*128 + head*32;
        const __nv_bfloat16* vb_ = v + (size_t)win*64*128 + head*32;
        unsigned short* vtb = (unsigned short*)Vt;
        #pragma unroll
        for (int i = 0; i < 4; i++) {
            int idx = tid + 64*i;
            int tok = idx >> 2, ch = idx & 3;
            size_t off = (size_t)tok*128 + ch*8;
            uint4 qq = *(const uint4*)(qb_ + off);
            uint4 kk = *(const uint4*)(kb_ + off);
            uint4 vv = *(const uint4*)(vb_ + off);
            *(uint4*)&Qs[tok*20 + ch*4] = qq;
            *(uint4*)&Ks[tok*20 + ch*4] = kk;
            unsigned vals[4] = {vv.x, vv.y, vv.z, vv.w};
            #pragma unroll
            for (int d = 0; d < 8; d++) {
                int n = ch*8 + d;
                vtb[(n*36 + (tok >> 1))*2 + (tok & 1)] =
                    (unsigned short)(vals[d >> 1] >> ((d & 1)*16));
            }
        }
    }
    __syncthreads();

    // ---- S = Q @ K^T (bf16): warp w covers key-cols [32w, 32w+32) ----
    float s[4][4][4];
    #pragma unroll
    for (int i = 0; i < 4; i++)
        #pragma unroll
        for (int j = 0; j < 4; j++)
            #pragma unroll
            for (int c = 0; c < 4; c++) s[i][j][c] = 0.f;

    const int nb0 = w*32;
    #pragma unroll
    for (int kk2 = 0; kk2 < 16; kk2 += 8) {
        unsigned afr[4][4], bfr[4][2];
        #pragma unroll
        for (int i = 0; i < 4; i++) {
            int base = (i*16 + lr)*20 + kk2 + lc;
            afr[i][0] = Qs[base];
            afr[i][1] = Qs[base + 8*20];
            afr[i][2] = Qs[base + 4];
            afr[i][3] = Qs[base + 8*20 + 4];
        }
        #pragma unroll
        for (int j = 0; j < 4; j++) {
            int nn = nb0 + j*8 + lr;
            bfr[j][0] = Ks[nn*20 + kk2 + lc];
            bfr[j][1] = Ks[nn*20 + kk2 + lc + 4];
        }
        #pragma unroll
        for (int i = 0; i < 4; i++)
            #pragma unroll
            for (int j = 0; j < 4; j++)
                mma_bf16(s[i][j], afr[i], bfr[j]);
    }

    // ---- in-register bias + mask + row-max (partial per warp) ----
    #pragma unroll
    for (int i = 0; i < 4; i++) {
        #pragma unroll
        for (int half = 0; half < 2; half++) {
            int r = i*16 + lr + half*8;
            int labr = lab_s[r];
            int ti = r >> 3, tj = r & 7;
            float m_ = -1e30f;
            #pragma unroll
            for (int j = 0; j < 4; j++) {
                #pragma unroll
                for (int e = 0; e < 2; e++) {
                    int c = nb0 + j*8 + 2*lc + e;
                    int ki = c >> 3, kj = c & 7;
                    float val = s[i][j][half*2 + e]
                              + rpb_s[(ti - ki + 7)*15 + (tj - kj + 7)];
                    if (lab_s[c] != labr) val -= 100.f;
                    s[i][j][half*2 + e] = val;
                    m_ = fmaxf(m_, val);
                }
            }
            m_ = fmaxf(m_, __shfl_xor_sync(0xffffffffu, m_, 1));
            m_ = fmaxf(m_, __shfl_xor_sync(0xffffffffu, m_, 2));
            if (lc == 0) redm[r*2 + w] = m_;
        }
    }
    __syncthreads();

    // ---- exp + row-sum (partial per warp) + pack P to smem ----
    #pragma unroll
    for (int i = 0; i < 4; i++) {
        #pragma unroll
        for (int half = 0; half < 2; half++) {
            int r = i*16 + lr + half*8;
            float mx = fmaxf(redm[r*2], redm[r*2 + 1]);
            float sum = 0.f;
            #pragma unroll
            for (int j = 0; j < 4; j++) {
                float e0 = __expf(s[i][j][half*2 + 0] - mx);
                float e1 = __expf(s[i][j][half*2 + 1] - mx);
                s[i][j][half*2 + 0] = e0;
                s[i][j][half*2 + 1] = e1;
                sum += e0 + e1;
                // P pair at cols (nb0 + j*8 + 2lc, +1) -> pair idx 16w + j*4 + lc
                Ps[r*36 + 16*w + j*4 + lc] = packbf(e0, e1);
            }
            sum += __shfl_xor_sync(0xffffffffu, sum, 1);
            sum += __shfl_xor_sync(0xffffffffu, sum, 2);
            if (lc == 0) redsum[r*2 + w] = sum;
        }
    }
    __syncthreads();

    // ---- O partial = P[:, 32w:32w+32) @ V[32w:32w+32, :] (bf16 mma) ----
    float o[4][4][4];
    #pragma unroll
    for (int i = 0; i < 4; i++)
        #pragma unroll
        for (int j = 0; j < 4; j++)
            #pragma unroll
            for (int c = 0; c < 4; c++) o[i][j][c] = 0.f;

    const int woff = 16*w;   // pair offset for this warp's k range
    #pragma unroll
    for (int kb = 0; kb < 2; kb++) {
        unsigned afr[4][4], bfr[4][2];
        #pragma unroll
        for (int i = 0; i < 4; i++) {
            int base = (i*16 + lr)*36 + woff + kb*8 + lc;
            afr[i][0] = Ps[base];
            afr[i][1] = Ps[base + 8*36];
            afr[i][2] = Ps[base + 4];
            afr[i][3] = Ps[base + 8*36 + 4];
        }
        #pragma unroll
        for (int j = 0; j < 4; j++) {
            int base = (j*8 + lr)*36 + woff + kb*8 + lc;
            bfr[j][0] = Vt[base];
            bfr[j][1] = Vt[base + 4];
        }
        #pragma unroll
        for (int i = 0; i < 4; i++)
            #pragma unroll
            for (int j = 0; j < 4; j++)
                mma_bf16(o[i][j], afr[i], bfr[j]);
    }
    __syncthreads();   // all Ps reads done before aliasing as Osum

    float* Osum = (float*)Ps;   // [64][34] fp32
    if (w == 1) {
        #pragma unroll
        for (int i = 0; i < 4; i++)
            #pragma unroll
            for (int j = 0; j < 4; j++) {
                int r0 = i*16 + lr;
                int n  = j*8 + 2*lc;
                *(float2*)&Osum[r0*34 + n]     = make_float2(o[i][j][0], o[i][j][1]);
                *(float2*)&Osum[(r0+8)*34 + n] = make_float2(o[i][j][2], o[i][j][3]);
            }
    }
    __syncthreads();
    if (w == 0) {
        #pragma unroll
        for (int i = 0; i < 4; i++) {
            #pragma unroll
            for (int half = 0; half < 2; half++) {
                int r = i*16 + lr + half*8;
                float inv = 1.f / (redsum[r*2] + redsum[r*2 + 1]);
                size_t ob = (size_t)win*64*128 + (size_t)r*128 + head*32;
                #pragma unroll
                for (int j = 0; j < 4; j++) {
                    int n = j*8 + 2*lc;
                    float v0 = (o[i][j][half*2 + 0] + Osum[r*34 + n])     * inv;
                    float v1 = (o[i][j][half*2 + 1] + Osum[r*34 + n + 1]) * inv;
                    *(unsigned*)&out[ob + n] = packbf(v0, v1);
                }
            }
        }
    }
}

// ---------------------------------------------------------------------------
extern "C" void kernel_launch(void* const* d_in, const int* in_sizes, int n_in,
                              void* d_out, int out_size)
{
    const float* hs   = (const float*)d_in[0];
    const float* l1s  = (const float*)d_in[1];
    const float* l1b  = (const float*)d_in[2];
    const float* qw   = (const float*)d_in[3];
    const float* qb   = (const float*)d_in[4];
    const float* kw   = (const float*)d_in[5];
    const float* kb   = (const float*)d_in[6];
    const float* vw   = (const float*)d_in[7];
    const float* vb   = (const float*)d_in[8];
    const float* pw   = (const float*)d_in[9];
    const float* pb   = (const float*)d_in[10];
    const float* rpb  = (const float*)d_in[11];
    const float* l2s  = (const float*)d_in[12];
    const float* l2b  = (const float*)d_in[13];
    const float* f1w  = (const float*)d_in[14];
    const float* f1b  = (const float*)d_in[15];
    const float* f2w  = (const float*)d_in[16];
    const float* f2b  = (const float*)d_in[17];
    float* outp = (float*)d_out;

    __nv_bfloat16 *xw, *qx, *kx, *vx, *ao, *dl, *l2, *hbuf, *wt;
    cudaGetSymbolAddress((void**)&xw,   g_xw);
    cudaGetSymbolAddress((void**)&qx,   g_q);
    cudaGetSymbolAddress((void**)&kx,   g_k);
    cudaGetSymbolAddress((void**)&vx,   g_v);
    cudaGetSymbolAddress((void**)&ao,   g_ao);
    cudaGetSymbolAddress((void**)&dl,   g_dl);
    cudaGetSymbolAddress((void**)&l2,   g_l2);
    cudaGetSymbolAddress((void**)&hbuf, g_h);
    cudaGetSymbolAddress((void**)&wt,   g_wt);

    __nv_bfloat16* qt  = wt;
    __nv_bfloat16* kt  = wt + 16384;
    __nv_bfloat16* vt  = wt + 32768;
    __nv_bfloat16* pt  = wt + 49152;
    __nv_bfloat16* f1t = wt + 65536;   // [512][128]
    __nv_bfloat16* f2t = wt + 131072;  // [128][512]

    cudaFuncSetAttribute(gemm_tc, cudaFuncAttributeMaxDynamicSharedMemorySize, GEMM_SMEM);

    const float qscale = 0.17677669529663687f;  // 1/sqrt(32)

    // 0. fused weight prep
    prep_all<<<768, 256>>>(qw, kw, vw, pw, f1w, f2w, wt);
    // 1. LN1 + shift + window partition (bf16 out)
    ln_kernel<<<MTOK/8, 256>>>(hs, l1s, l1b, xw, 1);
    // 2. fused QKV projections
    gemm_tc<<<dim3(3, MTOK/BM), 256, GEMM_SMEM>>>(xw, qt, qb, qx, kt, kb, kx, vt, vb, vx,
                                       128, 128, qscale, 0, nullptr, nullptr, nullptr, nullptr);
    // 3. windowed attention (all-bf16 mma, in-register softmax)
    attn_kernel<<<4096*4, 64>>>(qx, kx, vx, rpb, ao);
    // 4. proj -> delta bf16; LN2(hs[perm]+delta) -> l2
    gemm_tc<<<dim3(1, MTOK/BM), 256, GEMM_SMEM>>>(ao, pt, pb, dl, nullptr, nullptr, nullptr,
                                       nullptr, nullptr, nullptr,
                                       128, 128, 1.0f, 1, hs, l2, l2s, l2b);
    // 5. fc1 + GELU
    gemm_tc<<<dim3(4, MTOK/BM), 256, GEMM_SMEM>>>(l2, f1t, f1b, hbuf, nullptr, nullptr, nullptr,
                                       nullptr, nullptr, nullptr,
                                       512, 128, 1.0f, 2, nullptr, nullptr, nullptr, nullptr);
    // 6. fc2: out[perm] = acc + bias + hs[perm] + delta
    gemm_tc<<<dim3(1, MTOK/BM), 256, GEMM_SMEM>>>(hbuf, f2t, f2b, outp, nullptr, nullptr, nullptr,
                                       nullptr, nullptr, nullptr,
                                       128, 512, 1.0f, 3, hs, dl, nullptr, nullptr);
}

// round 8
// speedup vs baseline: 4.0170x; 1.0367x over previous
#include <cuda_runtime.h>
#include <cuda_bf16.h>
#include <math.h>

#define MTOK 262144   // B*H*W = 4*256*256
#define CDIM 128
#define HID  512

// ---------------- scratch (device globals: allocation-free) ----------------
__device__ __nv_bfloat16 g_xw[(size_t)MTOK*CDIM];  // LN1 + shift + window partition
__device__ __nv_bfloat16 g_q [(size_t)MTOK*CDIM];
__device__ __nv_bfloat16 g_k [(size_t)MTOK*CDIM];
__device__ __nv_bfloat16 g_v [(size_t)MTOK*CDIM];
__device__ __nv_bfloat16 g_ao[(size_t)MTOK*CDIM];  // attention output (window order)
__device__ __nv_bfloat16 g_dl[(size_t)MTOK*CDIM];  // delta = proj_out + bias (bf16, window order)
__device__ __nv_bfloat16 g_l2[(size_t)MTOK*CDIM];  // LN2(hs[perm] + delta)
__device__ __nv_bfloat16 g_wt[196608];             // transposed bf16 weights [N][K]

__device__ __forceinline__ int region(int a) { return a < 248 ? 0 : (a < 252 ? 1 : 2); }

__device__ __forceinline__ void mma_bf16(float c[4], const unsigned a[4], const unsigned b[2]) {
    asm volatile("mma.sync.aligned.m16n8k16.row.col.f32.bf16.bf16.f32 "
        "{%0,%1,%2,%3}, {%4,%5,%6,%7}, {%8,%9}, {%0,%1,%2,%3};\n"
        : "+f"(c[0]), "+f"(c[1]), "+f"(c[2]), "+f"(c[3])
        : "r"(a[0]), "r"(a[1]), "r"(a[2]), "r"(a[3]), "r"(b[0]), "r"(b[1]));
}
__device__ __forceinline__ void cp16(unsigned dst, const void* src) {
    asm volatile("cp.async.cg.shared.global [%0], [%1], 16;\n" :: "r"(dst), "l"(src));
}
#define CP_COMMIT asm volatile("cp.async.commit_group;\n" ::: "memory")
#define CP_WAIT1  asm volatile("cp.async.wait_group 1;\n" ::: "memory")
#define CP_WAIT0  asm volatile("cp.async.wait_group 0;\n" ::: "memory")

// window-order index m -> original token index (window reverse + roll(+4,+4))
__device__ __forceinline__ int perm_m(int m) {
    int b = m >> 16, w = (m >> 6) & 1023, t = m & 63;
    int wh = w >> 5, ww = w & 31, ti = t >> 3, tj = t & 7;
    int r = (wh*8 + ti + 4) & 255;
    int c = (ww*8 + tj + 4) & 255;
    return (b << 16) | (r << 8) | c;
}
__device__ __forceinline__ unsigned packbf(float a, float b) {
    __nv_bfloat162 t = __floats2bfloat162_rn(a, b);
    return *(unsigned*)&t;
}

// ---------------- fused weight prep: all six matrices in one launch --------
__global__ void prep_all(const float* __restrict__ qw, const float* __restrict__ kw,
                         const float* __restrict__ vw, const float* __restrict__ pw,
                         const float* __restrict__ f1w, const float* __restrict__ f2w,
                         __nv_bfloat16* __restrict__ wt)
{
    int idx = blockIdx.x * 256 + threadIdx.x;     // 0..196607
    float v;
    if (idx < 65536) {
        int seg = idx >> 14;
        int rel = idx & 16383;
        int n = rel >> 7, k = rel & 127;
        const float* src = seg == 0 ? qw : (seg == 1 ? kw : (seg == 2 ? vw : pw));
        v = src[k*128 + n];
    } else if (idx < 131072) {
        int rel = idx - 65536;            // f1t [512][128] <- f1w [128][512]
        int n = rel >> 7, k = rel & 127;
        v = f1w[k*512 + n];
    } else {
        int rel = idx - 131072;           // f2t [128][512] <- f2w [512][128]
        int n = rel >> 9, k = rel & 511;
        v = f2w[k*128 + n];
    }
    wt[idx] = __float2bfloat16(v);
}

// ---------------- LayerNorm (fused with shift+window gather), bf16 out -----
__global__ void ln_kernel(const float* __restrict__ in, const float* __restrict__ gamma,
                          const float* __restrict__ beta, __nv_bfloat16* __restrict__ out,
                          int gather)
{
    int token = blockIdx.x * 8 + (threadIdx.x >> 5);
    int lane  = threadIdx.x & 31;
    int src = gather ? perm_m(token) : token;
    float4 xv = ((const float4*)in)[(size_t)src*32 + lane];
    float s  = xv.x + xv.y + xv.z + xv.w;
    float sq = xv.x*xv.x + xv.y*xv.y + xv.z*xv.z + xv.w*xv.w;
    #pragma unroll
    for (int o = 16; o; o >>= 1) {
        s  += __shfl_xor_sync(0xffffffffu, s,  o);
        sq += __shfl_xor_sync(0xffffffffu, sq, o);
    }
    float mean = s * (1.f/128.f);
    float var  = sq * (1.f/128.f) - mean*mean;
    float rstd = rsqrtf(var + 1e-5f);
    float4 g  = ((const float4*)gamma)[lane];
    float4 bt = ((const float4*)beta)[lane];
    uint2 pk;
    pk.x = packbf((xv.x - mean)*rstd*g.x + bt.x, (xv.y - mean)*rstd*g.y + bt.y);
    pk.y = packbf((xv.z - mean)*rstd*g.z + bt.z, (xv.w - mean)*rstd*g.w + bt.w);
    ((uint2*)out)[(size_t)token*32 + lane] = pk;
}

// ---------------- bf16 tensor-core GEMM (QKV / proj+LN2) -------------------
#define BM 128
#define BN 128
#define BK 32
#define ASTR 20
#define BSTR 20
#define NST 3
#define SA_W (BM*ASTR)
#define SB_W (BN*BSTR)
#define GEMM_SMEM ((NST*(SA_W + SB_W))*4 + BM*4*4*2)

__global__ void __launch_bounds__(256, 2) gemm_tc(
    const __nv_bfloat16* __restrict__ A,
    const __nv_bfloat16* __restrict__ W0, const float* __restrict__ B0, void* __restrict__ C0v,
    const __nv_bfloat16* __restrict__ W1, const float* __restrict__ B1, void* __restrict__ C1v,
    const __nv_bfloat16* __restrict__ W2, const float* __restrict__ B2, void* __restrict__ C2v,
    int N, int K, float scale, int mode,
    const float* __restrict__ add, __nv_bfloat16* __restrict__ aux_bf,
    const float* __restrict__ gamma, const float* __restrict__ beta)
{
    extern __shared__ unsigned smem[];
    unsigned* AsB = smem;
    unsigned* BsB = smem + NST*SA_W;
    float* red_s = (float*)(smem + NST*(SA_W + SB_W));
    float* red_q = red_s + BM*4;

    const int tid  = threadIdx.x;
    const int lane = tid & 31;
    const int lr   = lane >> 2;
    const int lc   = lane & 3;
    const int w    = tid >> 5;
    const int wm   = w >> 2;
    const int wn   = w & 3;
    const int m0   = blockIdx.y * BM;

    const __nv_bfloat16* Bw; const float* bias; void* Cout; float sc; int n0;
    if (mode == 0) {
        int s = blockIdx.x;
        Bw   = s == 0 ? W0 : (s == 1 ? W1 : W2);
        bias = s == 0 ? B0 : (s == 1 ? B1 : B2);
        Cout = s == 0 ? C0v : (s == 1 ? C1v : C2v);
        sc   = s == 0 ? scale : 1.0f;
        n0   = 0;
    } else {
        Bw = W0; bias = B0; Cout = C0v; sc = 1.0f;
        n0 = blockIdx.x * BN;
    }

    const int grow = tid >> 2;
    const int gc8  = (tid & 3) << 3;

    const __nv_bfloat16* Ap0 = A  + (size_t)(m0 + grow) * K + gc8;
    const __nv_bfloat16* Ap1 = Ap0 + (size_t)64 * K;
    const __nv_bfloat16* Bp0 = Bw + (size_t)(n0 + grow) * K + gc8;
    const __nv_bfloat16* Bp1 = Bp0 + (size_t)64 * K;

    const unsigned a_base = (unsigned)__cvta_generic_to_shared(AsB);
    const unsigned b_base = (unsigned)__cvta_generic_to_shared(BsB);
    const unsigned a_s0 = a_base + (grow*ASTR + (tid & 3)*4)*4;
    const unsigned a_s1 = a_base + ((grow+64)*ASTR + (tid & 3)*4)*4;
    const unsigned b_s0 = b_base + (grow*BSTR + (tid & 3)*4)*4;
    const unsigned b_s1 = b_base + ((grow+64)*BSTR + (tid & 3)*4)*4;
    const unsigned SAB = SA_W*4, SBB = SB_W*4;

    const int stages = K >> 5;

    #define ISSUE(t, buf) { \
        int kt_ = (t) << 5; \
        cp16(a_s0 + (buf)*SAB, Ap0 + kt_); \
        cp16(a_s1 + (buf)*SAB, Ap1 + kt_); \
        cp16(b_s0 + (buf)*SBB, Bp0 + kt_); \
        cp16(b_s1 + (buf)*SBB, Bp1 + kt_); \
        CP_COMMIT; }

    ISSUE(0, 0);
    ISSUE(1, 1);
    CP_WAIT1;
    __syncthreads();

    float acc[4][4][4];
    #pragma unroll
    for (int i = 0; i < 4; i++)
        #pragma unroll
        for (int j = 0; j < 4; j++)
            #pragma unroll
            for (int c = 0; c < 4; c++) acc[i][j][c] = 0.f;

    const int a_off = (wm*64 + lr)*ASTR + lc;
    const int b_off = (wn*32 + lr)*BSTR + lc;

    for (int t = 0; t < stages; t++) {
        const unsigned* as = AsB + (t % NST)*SA_W;
        const unsigned* bs = BsB + (t % NST)*SB_W;
        #pragma unroll
        for (int kk2 = 0; kk2 < 16; kk2 += 8) {
            unsigned afr[4][4];
            #pragma unroll
            for (int i = 0; i < 4; i++) {
                int base = a_off + i*16*ASTR + kk2;
                afr[i][0] = as[base];
                afr[i][1] = as[base + 8*ASTR];
                afr[i][2] = as[base + 4];
                afr[i][3] = as[base + 8*ASTR + 4];
            }
            #pragma unroll
            for (int j = 0; j < 4; j++) {
                unsigned bfr[2];
                int bb = b_off + j*8*BSTR + kk2;
                bfr[0] = bs[bb];
                bfr[1] = bs[bb + 4];
                #pragma unroll
                for (int i = 0; i < 4; i++)
                    mma_bf16(acc[i][j], afr[i], bfr);
            }
        }
        if (t + 2 < stages) {
            ISSUE(t + 2, (t + 2) % NST);
            CP_WAIT1;
            __syncthreads();
        } else if (t + 1 < stages) {
            CP_WAIT0;
            __syncthreads();
        }
    }
    #undef ISSUE

    // ---------------- epilogue ----------------
    if (mode == 1) {
        __nv_bfloat16* Cd = (__nv_bfloat16*)Cout;
        #pragma unroll
        for (int i = 0; i < 4; i++) {
            #pragma unroll
            for (int half = 0; half < 2; half++) {
                int rl = wm*64 + i*16 + lr + half*8;
                int m  = m0 + rl;
                const float* hsrow = add + (size_t)perm_m(m) * 128;
                size_t drow = (size_t)m * 128;
                float s = 0.f, sq = 0.f;
                #pragma unroll
                for (int j = 0; j < 4; j++) {
                    int n = wn*32 + j*8 + 2*lc;
                    float d0 = acc[i][j][half*2 + 0] + bias[n];
                    float d1 = acc[i][j][half*2 + 1] + bias[n+1];
                    *(unsigned*)&Cd[drow + n] = packbf(d0, d1);
                    float v0 = d0 + hsrow[n];
                    float v1 = d1 + hsrow[n+1];
                    acc[i][j][half*2 + 0] = v0;
                    acc[i][j][half*2 + 1] = v1;
                    s  += v0 + v1;
                    sq += v0*v0 + v1*v1;
                }
                s  += __shfl_xor_sync(0xffffffffu, s, 1);
                s  += __shfl_xor_sync(0xffffffffu, s, 2);
                sq += __shfl_xor_sync(0xffffffffu, sq, 1);
                sq += __shfl_xor_sync(0xffffffffu, sq, 2);
                if (lc == 0) { red_s[rl*4 + wn] = s; red_q[rl*4 + wn] = sq; }
            }
        }
        __syncthreads();
        #pragma unroll
        for (int i = 0; i < 4; i++) {
            #pragma unroll
            for (int half = 0; half < 2; half++) {
                int rl = wm*64 + i*16 + lr + half*8;
                float s  = red_s[rl*4+0] + red_s[rl*4+1] + red_s[rl*4+2] + red_s[rl*4+3];
                float sq = red_q[rl*4+0] + red_q[rl*4+1] + red_q[rl*4+2] + red_q[rl*4+3];
                float mu = s * (1.f/128.f);
                float var = sq * (1.f/128.f) - mu*mu;
                float rstd = rsqrtf(var + 1e-5f);
                size_t base = (size_t)(m0 + rl) * 128;
                #pragma unroll
                for (int j = 0; j < 4; j++) {
                    int n = wn*32 + j*8 + 2*lc;
                    float l0 = (acc[i][j][half*2 + 0] - mu)*rstd*gamma[n]   + beta[n];
                    float l1 = (acc[i][j][half*2 + 1] - mu)*rstd*gamma[n+1] + beta[n+1];
                    *(unsigned*)&aux_bf[base + n] = packbf(l0, l1);
                }
            }
        }
    } else {
        __nv_bfloat16* Cb = (__nv_bfloat16*)Cout;
        #pragma unroll
        for (int i = 0; i < 4; i++) {
            #pragma unroll
            for (int half = 0; half < 2; half++) {
                int m = m0 + wm*64 + i*16 + lr + half*8;
                size_t dstrow = (size_t)m * N;
                #pragma unroll
                for (int j = 0; j < 4; j++) {
                    int n = wn*32 + j*8 + 2*lc;
                    int ng = n0 + n;
                    float v0 = (acc[i][j][half*2 + 0] + bias[ng]) * sc;
                    float v1 = (acc[i][j][half*2 + 1] + bias[ng+1]) * sc;
                    *(unsigned*)&Cb[dstrow + ng] = packbf(v0, v1);
                }
            }
        }
    }
}

// ---------------- fused MLP: fc1 + GELU (smem h) + fc2 + residuals ---------
// One block = 64 tokens, 256 threads = 8 warps (wm 0..1 rows, wn 0..3 cols).
// fc1: 4 chunks of 128 cols, W1t streamed (L2-resident), gelu -> Hs bf16.
// fc2: K=512 from Hs, W2t streamed. out[perm] = acc + b2 + hs[perm] + dl.
#define ASTR2 68    // A tile row stride (uints): 64 pairs + 4 pad
#define HSTR  260   // Hs row stride (uints): 256 pairs + 4 pad
#define BSTR2 20    // B stage row stride (uints): 16 pairs + 4 pad
#define MLP_SMEM ((64*ASTR2 + 64*HSTR + 2*128*BSTR2)*4)

__global__ void __launch_bounds__(256, 2) mlp_fused(
    const __nv_bfloat16* __restrict__ A,      // l2 (window order)
    const __nv_bfloat16* __restrict__ W1t,    // [512][128]
    const float* __restrict__ b1,
    const __nv_bfloat16* __restrict__ W2t,    // [128][512]
    const float* __restrict__ b2,
    const float* __restrict__ hs,             // original order fp32
    const __nv_bfloat16* __restrict__ dl,     // window order bf16
    float* __restrict__ outp)
{
    extern __shared__ unsigned sm[];
    unsigned* As = sm;                        // 64*68
    unsigned* Hs = sm + 64*ASTR2;             // 64*260
    unsigned* Bs = Hs + 64*HSTR;              // 2 * 128*20

    const int tid  = threadIdx.x;
    const int lane = tid & 31;
    const int lr   = lane >> 2;
    const int lc   = lane & 3;
    const int w    = tid >> 5;
    const int wm   = w >> 2;                  // 0..1
    const int wn   = w & 3;                   // 0..3
    const int m0   = blockIdx.x * 64;

    // load A tile (64 x 128 bf16), coalesced
    {
        const uint4* src = (const uint4*)(A + (size_t)m0 * 128);
        #pragma unroll
        for (int s = 0; s < 4; s++) {
            int slot = tid + 256*s;          // 0..1023
            int row = slot >> 4, c4 = slot & 15;
            *(uint4*)&As[row*ASTR2 + c4*4] = src[row*16 + c4];
        }
    }

    const unsigned bs_base = (unsigned)__cvta_generic_to_shared(Bs);
    const unsigned BSB = 128*BSTR2*4;
    const int brow = tid >> 1;               // unused placeholder (kept regs low)
    (void)brow;

    #define BISSUE(Wt, rowoff, Kw, ktoff, buf) { \
        _Pragma("unroll") \
        for (int s_ = 0; s_ < 2; s_++) { \
            int slot_ = tid + 256*s_; \
            int rw_ = slot_ >> 2, c_ = slot_ & 3; \
            cp16(bs_base + (buf)*BSB + (rw_*BSTR2 + c_*4)*4, \
                 (Wt) + (size_t)((rowoff) + rw_)*(Kw) + (ktoff) + c_*8); \
        } \
        CP_COMMIT; }

    const int a_row = wm*32 + lr;            // + i*16 + half*8
    float acc[2][4][4];

    // ---------------- fc1: 16 stages = 4 chunks x 4 k-steps ----------------
    BISSUE(W1t, 0, 128, 0, 0);
    for (int st = 0; st < 16; st++) {
        if ((st & 3) == 0) {
            #pragma unroll
            for (int i = 0; i < 2; i++)
                #pragma unroll
                for (int j = 0; j < 4; j++)
                    #pragma unroll
                    for (int c = 0; c < 4; c++) acc[i][j][c] = 0.f;
        }
        if (st + 1 < 16) { BISSUE(W1t, ((st+1) >> 2)*128, 128, ((st+1) & 3)*32, (st+1) & 1); CP_WAIT1; }
        else             { CP_WAIT0; }
        __syncthreads();
        {
            const unsigned* bs = Bs + (st & 1)*128*BSTR2;
            const int koff = (st & 3)*16;
            #pragma unroll
            for (int kk2 = 0; kk2 < 16; kk2 += 8) {
                unsigned afr[2][4];
                #pragma unroll
                for (int i = 0; i < 2; i++) {
                    int base = (a_row + i*16)*ASTR2 + koff + kk2 + lc;
                    afr[i][0] = As[base];
                    afr[i][1] = As[base + 8*ASTR2];
                    afr[i][2] = As[base + 4];
                    afr[i][3] = As[base + 8*ASTR2 + 4];
                }
                #pragma unroll
                for (int j = 0; j < 4; j++) {
                    unsigned bfr[2];
                    int bb = (wn*32 + j*8 + lr)*BSTR2 + kk2 + lc;
                    bfr[0] = bs[bb];
                    bfr[1] = bs[bb + 4];
                    #pragma unroll
                    for (int i = 0; i < 2; i++)
                        mma_bf16(acc[i][j], afr[i], bfr);
                }
            }
        }
        if ((st & 3) == 3) {
            // chunk epilogue: bias + gelu -> Hs
            int ch = st >> 2;
            #pragma unroll
            for (int i = 0; i < 2; i++) {
                #pragma unroll
                for (int half = 0; half < 2; half++) {
                    int row = a_row + i*16 + half*8;
                    #pragma unroll
                    for (int j = 0; j < 4; j++) {
                        int n = wn*32 + j*8 + 2*lc;
                        float v0 = acc[i][j][half*2 + 0] + b1[ch*128 + n];
                        float v1 = acc[i][j][half*2 + 1] + b1[ch*128 + n + 1];
                        v0 = 0.5f*v0*(1.0f + erff(v0*0.70710678118654752f));
                        v1 = 0.5f*v1*(1.0f + erff(v1*0.70710678118654752f));
                        Hs[row*HSTR + ch*64 + wn*16 + j*4 + lc] = packbf(v0, v1);
                    }
                }
            }
        }
        __syncthreads();
    }

    // ---------------- fc2: 16 k-stages of 32 over K=512 --------------------
    {
        #pragma unroll
        for (int i = 0; i < 2; i++)
            #pragma unroll
            for (int j = 0; j < 4; j++)
                #pragma unroll
                for (int c = 0; c < 4; c++) acc[i][j][c] = 0.f;
    }
    BISSUE(W2t, 0, 512, 0, 0);
    for (int st = 0; st < 16; st++) {
        if (st + 1 < 16) { BISSUE(W2t, 0, 512, (st+1)*32, (st+1) & 1); CP_WAIT1; }
        else             { CP_WAIT0; }
        __syncthreads();
        {
            const unsigned* bs = Bs + (st & 1)*128*BSTR2;
            const int koff = st*16;
            #pragma unroll
            for (int kk2 = 0; kk2 < 16; kk2 += 8) {
                unsigned afr[2][4];
                #pragma unroll
                for (int i = 0; i < 2; i++) {
                    int base = (a_row + i*16)*HSTR + koff + kk2 + lc;
                    afr[i][0] = Hs[base];
                    afr[i][1] = Hs[base + 8*HSTR];
                    afr[i][2] = Hs[base + 4];
                    afr[i][3] = Hs[base + 8*HSTR + 4];
                }
                #pragma unroll
                for (int j = 0; j < 4; j++) {
                    unsigned bfr[2];
                    int bb = (wn*32 + j*8 + lr)*BSTR2 + kk2 + lc;
                    bfr[0] = bs[bb];
                    bfr[1] = bs[bb + 4];
                    #pragma unroll
                    for (int i = 0; i < 2; i++)
                        mma_bf16(acc[i][j], afr[i], bfr);
                }
            }
        }
        __syncthreads();
    }

    // ---------------- final epilogue: residuals + perm scatter -------------
    #pragma unroll
    for (int i = 0; i < 2; i++) {
        #pragma unroll
        for (int half = 0; half < 2; half++) {
            int m = m0 + a_row + i*16 + half*8;
            size_t dstrow = (size_t)perm_m(m) * 128;
            const float* hsrow = hs + dstrow;
            const __nv_bfloat16* drow = dl + (size_t)m * 128;
            #pragma unroll
            for (int j = 0; j < 4; j++) {
                int n = wn*32 + j*8 + 2*lc;
                __nv_bfloat162 db = *(const __nv_bfloat162*)&drow[n];
                float v0 = acc[i][j][half*2 + 0] + b2[n]   + hsrow[n]   + __bfloat162float(db.x);
                float v1 = acc[i][j][half*2 + 1] + b2[n+1] + hsrow[n+1] + __bfloat162float(db.y);
                *(float2*)&outp[dstrow + n] = make_float2(v0, v1);
            }
        }
    }
    #undef BISSUE
}

// ---------------- windowed attention: all-bf16 mma, in-register softmax ----
__global__ void __launch_bounds__(64) attn_kernel(
    const __nv_bfloat16* __restrict__ q, const __nv_bfloat16* __restrict__ k,
    const __nv_bfloat16* __restrict__ v, const float* __restrict__ rpb,
    __nv_bfloat16* __restrict__ out)
{
    __shared__ unsigned Qs[64*20];
    __shared__ unsigned Ks[64*20];
    __shared__ unsigned Vt[32*36];
    __shared__ unsigned Ps[64*36];
    __shared__ float    rpb_s[225];
    __shared__ int      lab_s[64];
    __shared__ float    redm[128];
    __shared__ float    redsum[128];

    const int win  = blockIdx.x >> 2;
    const int head = blockIdx.x & 3;
    const int tid  = threadIdx.x;
    const int lane = tid & 31;
    const int lr   = lane >> 2;
    const int lc   = lane & 3;
    const int w    = tid >> 5;
    const int wloc = win & 1023;
    const int wh = wloc >> 5, ww = wloc & 31;

    for (int idx = tid; idx < 225; idx += 64) rpb_s[idx] = rpb[idx*4 + head];
    lab_s[tid] = 3*region(wh*8 + (tid >> 3)) + region(ww*8 + (tid & 7));

    {
        const __nv_bfloat16* qb_ = q + (size_t)win*64*128 + head*32;
        const __nv_bfloat16* kb_ = k + (size_t)win*64*128 + head*32;
        const __nv_bfloat16* vb_ = v + (size_t)win*64*128 + head*32;
        unsigned short* vtb = (unsigned short*)Vt;
        #pragma unroll
        for (int i = 0; i < 4; i++) {
            int idx = tid + 64*i;
            int tok = idx >> 2, ch = idx & 3;
            size_t off = (size_t)tok*128 + ch*8;
            uint4 qq = *(const uint4*)(qb_ + off);
            uint4 kk = *(const uint4*)(kb_ + off);
            uint4 vv = *(const uint4*)(vb_ + off);
            *(uint4*)&Qs[tok*20 + ch*4] = qq;
            *(uint4*)&Ks[tok*20 + ch*4] = kk;
            unsigned vals[4] = {vv.x, vv.y, vv.z, vv.w};
            #pragma unroll
            for (int d = 0; d < 8; d++) {
                int n = ch*8 + d;
                vtb[(n*36 + (tok >> 1))*2 + (tok & 1)] =
                    (unsigned short)(vals[d >> 1] >> ((d & 1)*16));
            }
        }
    }
    __syncthreads();

    float s[4][4][4];
    #pragma unroll
    for (int i = 0; i < 4; i++)
        #pragma unroll
        for (int j = 0; j < 4; j++)
            #pragma unroll
            for (int c = 0; c < 4; c++) s[i][j][c] = 0.f;

    const int nb0 = w*32;
    #pragma unroll
    for (int kk2 = 0; kk2 < 16; kk2 += 8) {
        unsigned afr[4][4], bfr[4][2];
        #pragma unroll
        for (int i = 0; i < 4; i++) {
            int base = (i*16 + lr)*20 + kk2 + lc;
            afr[i][0] = Qs[base];
            afr[i][1] = Qs[base + 8*20];
            afr[i][2] = Qs[base + 4];
            afr[i][3] = Qs[base + 8*20 + 4];
        }
        #pragma unroll
        for (int j = 0; j < 4; j++) {
            int nn = nb0 + j*8 + lr;
            bfr[j][0] = Ks[nn*20 + kk2 + lc];
            bfr[j][1] = Ks[nn*20 + kk2 + lc + 4];
        }
        #pragma unroll
        for (int i = 0; i < 4; i++)
            #pragma unroll
            for (int j = 0; j < 4; j++)
                mma_bf16(s[i][j], afr[i], bfr[j]);
    }

    #pragma unroll
    for (int i = 0; i < 4; i++) {
        #pragma unroll
        for (int half = 0; half < 2; half++) {
            int r = i*16 + lr + half*8;
            int labr = lab_s[r];
            int ti = r >> 3, tj = r & 7;
            float m_ = -1e30f;
            #pragma unroll
            for (int j = 0; j < 4; j++) {
                #pragma unroll
                for (int e = 0; e < 2; e++) {
                    int c = nb0 + j*8 + 2*lc + e;
                    int ki = c >> 3, kj = c & 7;
                    float val = s[i][j][half*2 + e]
                              + rpb_s[(ti - ki + 7)*15 + (tj - kj + 7)];
                    if (lab_s[c] != labr) val -= 100.f;
                    s[i][j][half*2 + e] = val;
                    m_ = fmaxf(m_, val);
                }
            }
            m_ = fmaxf(m_, __shfl_xor_sync(0xffffffffu, m_, 1));
            m_ = fmaxf(m_, __shfl_xor_sync(0xffffffffu, m_, 2));
            if (lc == 0) redm[r*2 + w] = m_;
        }
    }
    __syncthreads();

    #pragma unroll
    for (int i = 0; i < 4; i++) {
        #pragma unroll
        for (int half = 0; half < 2; half++) {
            int r = i*16 + lr + half*8;
            float mx = fmaxf(redm[r*2], redm[r*2 + 1]);
            float sum = 0.f;
            #pragma unroll
            for (int j = 0; j < 4; j++) {
                float e0 = __expf(s[i][j][half*2 + 0] - mx);
                float e1 = __expf(s[i][j][half*2 + 1] - mx);
                s[i][j][half*2 + 0] = e0;
                s[i][j][half*2 + 1] = e1;
                sum += e0 + e1;
                Ps[r*36 + 16*w + j*4 + lc] = packbf(e0, e1);
            }
            sum += __shfl_xor_sync(0xffffffffu, sum, 1);
            sum += __shfl_xor_sync(0xffffffffu, sum, 2);
            if (lc == 0) redsum[r*2 + w] = sum;
        }
    }
    __syncthreads();

    float o[4][4][4];
    #pragma unroll
    for (int i = 0; i < 4; i++)
        #pragma unroll
        for (int j = 0; j < 4; j++)
            #pragma unroll
            for (int c = 0; c < 4; c++) o[i][j][c] = 0.f;

    const int woff = 16*w;
    #pragma unroll
    for (int kb = 0; kb < 2; kb++) {
        unsigned afr[4][4], bfr[4][2];
        #pragma unroll
        for (int i = 0; i < 4; i++) {
            int base = (i*16 + lr)*36 + woff + kb*8 + lc;
            afr[i][0] = Ps[base];
            afr[i][1] = Ps[base + 8*36];
            afr[i][2] = Ps[base + 4];
            afr[i][3] = Ps[base + 8*36 + 4];
        }
        #pragma unroll
        for (int j = 0; j < 4; j++) {
            int base = (j*8 + lr)*36 + woff + kb*8 + lc;
            bfr[j][0] = Vt[base];
            bfr[j][1] = Vt[base + 4];
        }
        #pragma unroll
        for (int i = 0; i < 4; i++)
            #pragma unroll
            for (int j = 0; j < 4; j++)
                mma_bf16(o[i][j], afr[i], bfr[j]);
    }
    __syncthreads();

    float* Osum = (float*)Ps;
    if (w == 1) {
        #pragma unroll
        for (int i = 0; i < 4; i++)
            #pragma unroll
            for (int j = 0; j < 4; j++) {
                int r0 = i*16 + lr;
                int n  = j*8 + 2*lc;
                *(float2*)&Osum[r0*34 + n]     = make_float2(o[i][j][0], o[i][j][1]);
                *(float2*)&Osum[(r0+8)*34 + n] = make_float2(o[i][j][2], o[i][j][3]);
            }
    }
    __syncthreads();
    if (w == 0) {
        #pragma unroll
        for (int i = 0; i < 4; i++) {
            #pragma unroll
            for (int half = 0; half < 2; half++) {
                int r = i*16 + lr + half*8;
                float inv = 1.f / (redsum[r*2] + redsum[r*2 + 1]);
                size_t ob = (size_t)win*64*128 + (size_t)r*128 + head*32;
                #pragma unroll
                for (int j = 0; j < 4; j++) {
                    int n = j*8 + 2*lc;
                    float v0 = (o[i][j][half*2 + 0] + Osum[r*34 + n])     * inv;
                    float v1 = (o[i][j][half*2 + 1] + Osum[r*34 + n + 1]) * inv;
                    *(unsigned*)&out[ob + n] = packbf(v0, v1);
                }
            }
        }
    }
}

// ---------------------------------------------------------------------------
extern "C" void kernel_launch(void* const* d_in, const int* in_sizes, int n_in,
                              void* d_out, int out_size)
{
    const float* hs   = (const float*)d_in[0];
    const float* l1s  = (const float*)d_in[1];
    const float* l1b  = (const float*)d_in[2];
    const float* qw   = (const float*)d_in[3];
    const float* qb   = (const float*)d_in[4];
    const float* kw   = (const float*)d_in[5];
    const float* kb   = (const float*)d_in[6];
    const float* vw   = (const float*)d_in[7];
    const float* vb   = (const float*)d_in[8];
    const float* pw   = (const float*)d_in[9];
    const float* pb   = (const float*)d_in[10];
    const float* rpb  = (const float*)d_in[11];
    const float* l2s  = (const float*)d_in[12];
    const float* l2b  = (const float*)d_in[13];
    const float* f1w  = (const float*)d_in[14];
    const float* f1b  = (const float*)d_in[15];
    const float* f2w  = (const float*)d_in[16];
    const float* f2b  = (const float*)d_in[17];
    float* outp = (float*)d_out;

    __nv_bfloat16 *xw, *qx, *kx, *vx, *ao, *dl, *l2, *wt;
    cudaGetSymbolAddress((void**)&xw,   g_xw);
    cudaGetSymbolAddress((void**)&qx,   g_q);
    cudaGetSymbolAddress((void**)&kx,   g_k);
    cudaGetSymbolAddress((void**)&vx,   g_v);
    cudaGetSymbolAddress((void**)&ao,   g_ao);
    cudaGetSymbolAddress((void**)&dl,   g_dl);
    cudaGetSymbolAddress((void**)&l2,   g_l2);
    cudaGetSymbolAddress((void**)&wt,   g_wt);

    __nv_bfloat16* qt  = wt;
    __nv_bfloat16* kt  = wt + 16384;
    __nv_bfloat16* vt  = wt + 32768;
    __nv_bfloat16* pt  = wt + 49152;
    __nv_bfloat16* f1t = wt + 65536;   // [512][128]
    __nv_bfloat16* f2t = wt + 131072;  // [128][512]

    cudaFuncSetAttribute(gemm_tc,   cudaFuncAttributeMaxDynamicSharedMemorySize, GEMM_SMEM);
    cudaFuncSetAttribute(mlp_fused, cudaFuncAttributeMaxDynamicSharedMemorySize, MLP_SMEM);

    const float qscale = 0.17677669529663687f;  // 1/sqrt(32)

    // 0. fused weight prep
    prep_all<<<768, 256>>>(qw, kw, vw, pw, f1w, f2w, wt);
    // 1. LN1 + shift + window partition (bf16 out)
    ln_kernel<<<MTOK/8, 256>>>(hs, l1s, l1b, xw, 1);
    // 2. fused QKV projections
    gemm_tc<<<dim3(3, MTOK/BM), 256, GEMM_SMEM>>>(xw, qt, qb, qx, kt, kb, kx, vt, vb, vx,
                                       128, 128, qscale, 0, nullptr, nullptr, nullptr, nullptr);
    // 3. windowed attention
    attn_kernel<<<4096*4, 64>>>(qx, kx, vx, rpb, ao);
    // 4. proj -> delta bf16; LN2(hs[perm]+delta) -> l2
    gemm_tc<<<dim3(1, MTOK/BM), 256, GEMM_SMEM>>>(ao, pt, pb, dl, nullptr, nullptr, nullptr,
                                       nullptr, nullptr, nullptr,
                                       128, 128, 1.0f, 1, hs, l2, l2s, l2b);
    // 5+6. fused MLP: fc1 + GELU + fc2 + residuals -> out[perm]
    mlp_fused<<<MTOK/64, 256, MLP_SMEM>>>(l2, f1t, f1b, f2t, f2b, hs, dl, outp);
}